// round 14
// baseline (speedup 1.0000x reference)
#include <cuda_runtime.h>
#include <math.h>

#define BATCH   1024
#define HALF    512
#define NT      10
#define PADDED  30
#define DEPTH   4
#define LAYERS  2
#define NHEADS  2
#define NCLS    10

typedef unsigned long long u64;

// g_mats layout (each matrix = 4 float2, row-major 2x2):
//   stem   : [0,120)    (t*4+l)*3+w
//   attn   : [120,600)  (((lay*2+h)*3+g)*4+l)*10+w
//   ffn    : [600,840)  ((lay*10+t)*4+l)*3+w
//   reduce : [840,960)  (t*4+l)*3+w
__device__ float2 g_mats[960 * 4];
__device__ float  g_H[BATCH * PADDED];
__device__ float  g_attn[BATCH * PADDED * NHEADS];
__device__ int    g_cnt[LAYERS][BATCH];

// ================= compile-time GF(2) mask tables =================
__host__ __device__ constexpr int parity(unsigned x) {
    int p = 0; while (x) { p ^= (int)(x & 1u); x >>= 1; } return p;
}

struct Masks {
    unsigned pm[DEPTH][NT];
    unsigned am[DEPTH][NT];
    unsigned zm[NT];
};

__host__ __device__ constexpr Masks make_masks() {
    Masks M{};
    for (int l = 0; l < DEPTH; l++) {
        unsigned R[NT]{}, Ri[NT]{};
        for (int u = 0; u < NT; u++) { R[u] = 1u << u; Ri[u] = 1u << u; }
        for (int ll = 0; ll < l; ll++) {
            int r = ll + 1;
            for (int i = 0; i < NT; i++) R[(i + r) % NT] ^= R[i];
        }
        for (int ll = l - 1; ll >= 0; ll--) {
            int r = ll + 1;
            for (int i = NT - 1; i >= 0; i--) Ri[(i + r) % NT] ^= Ri[i];
        }
        for (int w = 0; w < NT; w++) {
            unsigned m = 0;
            for (int u = 0; u < NT; u++) if ((Ri[u] >> w) & 1u) m |= 1u << u;
            M.pm[l][w] = m;
            M.am[l][w] = R[w];
        }
    }
    unsigned R[NT]{};
    for (int u = 0; u < NT; u++) R[u] = 1u << u;
    for (int ll = 0; ll < DEPTH; ll++) {
        int r = ll + 1;
        for (int i = 0; i < NT; i++) R[(i + r) % NT] ^= R[i];
    }
    for (int w = 0; w < NT; w++) M.zm[w] = R[w];
    return M;
}

struct Masks2 {
    unsigned pm[3][NT];
    unsigned am[3][NT];
    unsigned zm[NT];
    int posq[NT];
};

__host__ __device__ constexpr Masks2 make_masks2() {
    Masks M = make_masks();
    unsigned bestS = 0x1Fu; int bestScore = -1;
    for (unsigned S = 0; S < 1024u; S++) {
        int pc = 0;
        for (int q = 0; q < NT; q++) pc += (int)((S >> q) & 1u);
        if (pc != 5) continue;
        int score = 0;
        for (int l = 1; l < DEPTH; l++)
            for (int w = 0; w < NT; w++)
                if ((M.pm[l][w] & ~S & 0x3FFu) == 0u) score++;
        if (score > bestScore) { bestScore = score; bestS = S; }
    }
    int qpos[NT]{};
    Masks2 R{};
    {
        int lp = 0, hp = 5;
        for (int q = 0; q < NT; q++) {
            int p = ((bestS >> q) & 1u) ? lp++ : hp++;
            qpos[q] = p;
        }
        for (int q = 0; q < NT; q++) R.posq[qpos[q]] = q;
    }
    for (int l = 1; l < DEPTH; l++)
        for (int w = 0; w < NT; w++) {
            unsigned pm2 = 0, am2 = 0;
            for (int q = 0; q < NT; q++) {
                if ((M.pm[l][w] >> q) & 1u) pm2 |= 1u << qpos[q];
                if ((M.am[l][w] >> q) & 1u) am2 |= 1u << qpos[q];
            }
            R.pm[l - 1][w] = pm2;
            R.am[l - 1][w] = am2;
        }
    for (int w = 0; w < NT; w++) {
        unsigned z2 = 0;
        for (int q = 0; q < NT; q++) if ((M.zm[w] >> q) & 1u) z2 |= 1u << qpos[q];
        R.zm[w] = z2;
    }
    return R;
}
constexpr Masks2 MK2 = make_masks2();

// ================= packed f32x2 helpers =================
__device__ __forceinline__ u64 pack2(float lo, float hi) {
    u64 r; asm("mov.b64 %0, {%1,%2};" : "=l"(r) : "f"(lo), "f"(hi)); return r;
}
__device__ __forceinline__ float2 unpack2(u64 a) {
    float2 f; asm("mov.b64 {%0,%1}, %2;" : "=f"(f.x), "=f"(f.y) : "l"(a)); return f;
}
__device__ __forceinline__ u64 swap2(u64 a) {
    u64 r; asm("{ .reg .b32 lo, hi; mov.b64 {lo,hi}, %1; mov.b64 %0, {hi,lo}; }" : "=l"(r) : "l"(a)); return r;
}
__device__ __forceinline__ u64 f2fma(u64 a, u64 b, u64 c) {
    u64 r; asm("fma.rn.f32x2 %0, %1, %2, %3;" : "=l"(r) : "l"(a), "l"(b), "l"(c)); return r;
}
__device__ __forceinline__ u64 f2mul(u64 a, u64 b) {
    u64 r; asm("mul.rn.f32x2 %0, %1, %2;" : "=l"(r) : "l"(a), "l"(b)); return r;
}
__device__ __forceinline__ u64 shfl64_xor(u64 v, int m) {
    unsigned lo = (unsigned)v, hi = (unsigned)(v >> 32);
    lo = __shfl_xor_sync(0xffffffffu, lo, m);
    hi = __shfl_xor_sync(0xffffffffu, hi, m);
    return ((u64)hi << 32) | lo;
}

__device__ __forceinline__ float2 cmulf(float2 a, float2 b) {
    return make_float2(a.x * b.x - a.y * b.y, a.x * b.y + a.y * b.x);
}

// ================= SoA butterfly =================
__device__ __forceinline__ void soa_bfly(u64 xr, u64 xi, u64 yr, u64 yi,
                                         u64 CX, u64 cyp, u64 cyq, u64 dxp,
                                         u64 DYRE, u64 DYIM, u64& nr, u64& ni) {
    nr = f2fma(CX, xr, f2fma(cyp, xi, f2fma(dxp, yr, f2mul(DYRE, yi))));
    ni = f2fma(CX, xi, f2fma(cyq, xr, f2fma(dxp, yi, f2mul(DYIM, yr))));
}

// Case A: pure local, bit4 not in pair mask
template<unsigned MLO4, unsigned ALO4, int J>
__device__ __forceinline__ void loopA(u64* re, u64* im, u64 CX, u64 cy0, u64 cy1,
                                      u64 dx0, u64 dx1, u64 DYRE, u64 DYIM) {
    if constexpr (J < 16) {
        constexpr unsigned LOW = MLO4 & (0u - MLO4);
        if constexpr ((J & (int)LOW) == 0) {
            constexpr int J2 = J ^ (int)MLO4;
            constexpr int P  = parity(ALO4 & (unsigned)J);
            constexpr int P2 = parity(ALO4 & (unsigned)J2);
            u64 ar = re[J], ai = im[J], br = re[J2], bi = im[J2];
            u64 nr1, ni1, nr2, ni2;
            soa_bfly(ar, ai, br, bi, CX, P  ? cy1 : cy0, P  ? cy0 : cy1, P  ? dx1 : dx0, DYRE, DYIM, nr1, ni1);
            soa_bfly(br, bi, ar, ai, CX, P2 ? cy1 : cy0, P2 ? cy0 : cy1, P2 ? dx1 : dx0, DYRE, DYIM, nr2, ni2);
            re[J] = nr1; im[J] = ni1; re[J2] = nr2; im[J2] = ni2;
        }
        loopA<MLO4, ALO4, J + 1>(re, im, CX, cy0, cy1, dx0, dx1, DYRE, DYIM);
    }
}

// Case B: pair mask == bit4 only
template<unsigned ALO4, int J>
__device__ __forceinline__ void loopB(u64* re, u64* im, u64 CX, u64 cy0, u64 cy1,
                                      u64 dx0, u64 dx1, u64 DYRE, u64 DYIM) {
    if constexpr (J < 16) {
        constexpr int P = parity(ALO4 & (unsigned)J);
        u64 yr = swap2(re[J]), yi = swap2(im[J]);
        u64 nr, ni;
        soa_bfly(re[J], im[J], yr, yi, CX, P ? cy1 : cy0, P ? cy0 : cy1, P ? dx1 : dx0, DYRE, DYIM, nr, ni);
        re[J] = nr; im[J] = ni;
        loopB<ALO4, J + 1>(re, im, CX, cy0, cy1, dx0, dx1, DYRE, DYIM);
    }
}

// Case C: local with bit4 + low bits
template<unsigned MLO4, unsigned ALO4, int J>
__device__ __forceinline__ void loopC(u64* re, u64* im, u64 CX, u64 cy0, u64 cy1,
                                      u64 dx0, u64 dx1, u64 DYRE, u64 DYIM) {
    if constexpr (J < 16) {
        constexpr unsigned LOW = MLO4 & (0u - MLO4);
        if constexpr ((J & (int)LOW) == 0) {
            constexpr int J2 = J ^ (int)MLO4;
            constexpr int P  = parity(ALO4 & (unsigned)J);
            constexpr int P2 = parity(ALO4 & (unsigned)J2);
            u64 y1r = swap2(re[J2]), y1i = swap2(im[J2]);
            u64 y2r = swap2(re[J]),  y2i = swap2(im[J]);
            u64 nr1, ni1, nr2, ni2;
            soa_bfly(re[J],  im[J],  y1r, y1i, CX, P  ? cy1 : cy0, P  ? cy0 : cy1, P  ? dx1 : dx0, DYRE, DYIM, nr1, ni1);
            soa_bfly(re[J2], im[J2], y2r, y2i, CX, P2 ? cy1 : cy0, P2 ? cy0 : cy1, P2 ? dx1 : dx0, DYRE, DYIM, nr2, ni2);
            re[J] = nr1; im[J] = ni1; re[J2] = nr2; im[J2] = ni2;
        }
        loopC<MLO4, ALO4, J + 1>(re, im, CX, cy0, cy1, dx0, dx1, DYRE, DYIM);
    }
}

// Case D: lane bits only
template<unsigned MHI, unsigned MB4, unsigned ALO4, int J>
__device__ __forceinline__ void loopD(u64* re, u64* im, u64 CX, u64 cy0, u64 cy1,
                                      u64 dx0, u64 dx1, u64 DYRE, u64 DYIM) {
    if constexpr (J < 16) {
        constexpr int P = parity(ALO4 & (unsigned)J);
        u64 yr = shfl64_xor(re[J], (int)MHI);
        u64 yi = shfl64_xor(im[J], (int)MHI);
        if constexpr (MB4) { yr = swap2(yr); yi = swap2(yi); }
        u64 nr, ni;
        soa_bfly(re[J], im[J], yr, yi, CX, P ? cy1 : cy0, P ? cy0 : cy1, P ? dx1 : dx0, DYRE, DYIM, nr, ni);
        re[J] = nr; im[J] = ni;
        loopD<MHI, MB4, ALO4, J + 1>(re, im, CX, cy0, cy1, dx0, dx1, DYRE, DYIM);
    }
}

// Case F: lane + local bits
template<unsigned MLO4, unsigned MB4, unsigned MHI, unsigned ALO4, int J>
__device__ __forceinline__ void loopF(u64* re, u64* im, u64 CX, u64 cy0, u64 cy1,
                                      u64 dx0, u64 dx1, u64 DYRE, u64 DYIM) {
    if constexpr (J < 16) {
        constexpr unsigned LOW = MLO4 & (0u - MLO4);
        if constexpr ((J & (int)LOW) == 0) {
            constexpr int J2 = J ^ (int)MLO4;
            constexpr int P  = parity(ALO4 & (unsigned)J);
            constexpr int P2 = parity(ALO4 & (unsigned)J2);
            u64 y1r = shfl64_xor(re[J2], (int)MHI);
            u64 y1i = shfl64_xor(im[J2], (int)MHI);
            u64 y2r = shfl64_xor(re[J],  (int)MHI);
            u64 y2i = shfl64_xor(im[J],  (int)MHI);
            if constexpr (MB4) {
                y1r = swap2(y1r); y1i = swap2(y1i);
                y2r = swap2(y2r); y2i = swap2(y2i);
            }
            u64 nr1, ni1, nr2, ni2;
            soa_bfly(re[J],  im[J],  y1r, y1i, CX, P  ? cy1 : cy0, P  ? cy0 : cy1, P  ? dx1 : dx0, DYRE, DYIM, nr1, ni1);
            soa_bfly(re[J2], im[J2], y2r, y2i, CX, P2 ? cy1 : cy0, P2 ? cy0 : cy1, P2 ? dx1 : dx0, DYRE, DYIM, nr2, ni2);
            re[J] = nr1; im[J] = ni1; re[J2] = nr2; im[J2] = ni2;
        }
        loopF<MLO4, MB4, MHI, ALO4, J + 1>(re, im, CX, cy0, cy1, dx0, dx1, DYRE, DYIM);
    }
}

template<int L, int W>
__device__ __forceinline__ void apply_gate(u64* re, u64* im,
                                           const float2* __restrict__ gm, int lane) {
    constexpr unsigned m    = MK2.pm[L][W];
    constexpr unsigned a    = MK2.am[L][W];
    constexpr unsigned mlo4 = m & 15u;
    constexpr unsigned mb4  = (m >> 4) & 1u;
    constexpr unsigned mhi  = (m >> 5) & 31u;
    constexpr unsigned alo4 = a & 15u;
    constexpr unsigned ab4  = (a >> 4) & 1u;
    constexpr unsigned ahi  = (a >> 5) & 31u;
    float2 g00 = gm[((L + 1) * 10 + W) * 4 + 0];
    float2 g01 = gm[((L + 1) * 10 + W) * 4 + 1];
    float cx = g00.x, cy = g00.y, dx = g01.x, dy = g01.y;
    u64 CX   = pack2(cx, cx);
    u64 CY0  = pack2(-cy, ab4 ? cy : -cy);
    u64 DX0  = pack2(dx, ab4 ? -dx : dx);
    u64 DYRE = pack2(-dy, -dy);
    u64 DYIM = pack2(dy, dy);
    constexpr u64 SGN = 0x8000000080000000ull;
    u64 CY1 = CY0 ^ SGN;
    u64 DX1 = DX0 ^ SGN;
    int plane = (int)(__popc(ahi & (unsigned)lane) & 1);
    u64 cy0 = plane ? CY1 : CY0, cy1 = plane ? CY0 : CY1;
    u64 dx0 = plane ? DX1 : DX0, dx1 = plane ? DX0 : DX1;
    if constexpr (mhi == 0u && mb4 == 0u) {
        loopA<mlo4, alo4, 0>(re, im, CX, cy0, cy1, dx0, dx1, DYRE, DYIM);
    } else if constexpr (mhi == 0u && mlo4 == 0u) {
        loopB<alo4, 0>(re, im, CX, cy0, cy1, dx0, dx1, DYRE, DYIM);
    } else if constexpr (mhi == 0u) {
        loopC<mlo4, alo4, 0>(re, im, CX, cy0, cy1, dx0, dx1, DYRE, DYIM);
    } else if constexpr (mlo4 == 0u) {
        loopD<mhi, mb4, alo4, 0>(re, im, CX, cy0, cy1, dx0, dx1, DYRE, DYIM);
    } else {
        loopF<mlo4, mb4, mhi, alo4, 0>(re, im, CX, cy0, cy1, dx0, dx1, DYRE, DYIM);
    }
}

template<int G>
__device__ __forceinline__ void run_gates(u64* re, u64* im,
                                          const float2* __restrict__ gm, int lane) {
    if constexpr (G < 3 * NT) {
        apply_gate<G / NT, G % NT>(re, im, gm, lane);
        run_gates<G + 1>(re, im, gm, lane);
    }
}

// ================= measurement: packed |amp|^2 + packed FWHT =================
template<int K, int J>
__device__ __forceinline__ void fwht_stage_p(u64* pp, u64 ONE, u64 NEG) {
    if constexpr (J < 16) {
        if constexpr ((J & (1 << K)) == 0) {
            constexpr int J2 = J | (1 << K);
            u64 a = pp[J], b = pp[J2];
            pp[J]  = f2fma(ONE, b, a);
            pp[J2] = f2fma(NEG, b, a);
        }
        fwht_stage_p<K, J + 1>(pp, ONE, NEG);
    }
}
template<int K>
__device__ __forceinline__ void fwht_p(u64* pp, u64 ONE, u64 NEG) {
    if constexpr (K < 4) {
        fwht_stage_p<K, 0>(pp, ONE, NEG);
        fwht_p<K + 1>(pp, ONE, NEG);
    }
}
template<int W>
__device__ __forceinline__ void meas_from_p(const u64* pp, float* res, int lane) {
    if constexpr (W < NT) {
        constexpr unsigned z   = MK2.zm[W];
        constexpr unsigned idx = z & 15u;
        constexpr unsigned b4  = (z >> 4) & 1u;
        constexpr unsigned zhi = (z >> 5) & 31u;
        float2 v = unpack2(pp[idx]);
        float acc = b4 ? (v.x - v.y) : (v.x + v.y);
        if ((int)(__popc(zhi & (unsigned)lane) & 1)) acc = -acc;
        res[W] = acc;
        meas_from_p<W + 1>(pp, res, lane);
    }
}

// compile-time posq gather of embedding factors into position order
template<int P>
__device__ __forceinline__ void gather_factors(float2* fa, float2* fb, float2 va, float2 vb) {
    if constexpr (P < NT) {
        constexpr int q = MK2.posq[P];
        fa[P].x = __shfl_sync(0xffffffffu, va.x, q);
        fa[P].y = __shfl_sync(0xffffffffu, va.y, q);
        fb[P].x = __shfl_sync(0xffffffffu, vb.x, q);
        fb[P].y = __shfl_sync(0xffffffffu, vb.y, q);
        gather_factors<P + 1>(fa, fb, va, vb);
    }
}

// ================= 3-qubit register circuit =================
__device__ __forceinline__ float2 cadd3(float2 a, float2 b) {
    return make_float2(a.x + b.x, a.y + b.y);
}
__device__ __forceinline__ void run3(float x0, float x1, float x2,
                                     const float2* M, float E[3]) {
    float c[3], s[3];
    __sincosf(0.5f * x0, &s[0], &c[0]);
    __sincosf(0.5f * x1, &s[1], &c[1]);
    __sincosf(0.5f * x2, &s[2], &c[2]);
    float2 a[8];
#pragma unroll
    for (int i = 0; i < 8; i++) {
        float v = ((i >> 2) & 1 ? s[0] : c[0]) *
                  ((i >> 1) & 1 ? s[1] : c[1]) *
                  ((i      ) & 1 ? s[2] : c[2]);
        a[i] = make_float2(v, 0.f);
    }
#pragma unroll
    for (int l = 0; l < 4; l++) {
#pragma unroll
        for (int w = 0; w < 3; w++) {
            const float2* m = M + (l * 3 + w) * 4;
            const int p = 2 - w;
#pragma unroll
            for (int i0 = 0; i0 < 8; i0++) {
                if (i0 & (1 << p)) continue;
                int i1 = i0 | (1 << p);
                float2 A = a[i0], B = a[i1];
                a[i0] = cadd3(cmulf(m[0], A), cmulf(m[1], B));
                a[i1] = cadd3(cmulf(m[2], A), cmulf(m[3], B));
            }
        }
        const int r = (l & 1) + 1;
#pragma unroll
        for (int i = 0; i < 3; i++) {
            int pc = 2 - i;
            int pt = 2 - ((i + r) % 3);
#pragma unroll
            for (int idx = 0; idx < 8; idx++) {
                if (((idx >> pc) & 1) && !((idx >> pt) & 1)) {
                    int j = idx | (1 << pt);
                    float2 t = a[idx]; a[idx] = a[j]; a[j] = t;
                }
            }
        }
    }
    E[0] = E[1] = E[2] = 0.f;
#pragma unroll
    for (int i = 0; i < 8; i++) {
        float p = a[i].x * a[i].x + a[i].y * a[i].y;
        E[0] += (i & 4) ? -p : p;
        E[1] += (i & 2) ? -p : p;
        E[2] += (i & 1) ? -p : p;
    }
}

// ====== warp-level epilogues (executed by the last-arriving warp of b) =======
// layer-0: W_O dot + residual + FFN -> g_H
__device__ void tail_wo_ffn(int b, int lane, const float* __restrict__ W_O) {
    const int lay = 0;
    float newH = 0.f;
    if (lane < 30) {
        const float4* wrow = (const float4*)(W_O + (lay * 30 + lane) * 60);
        const float4* arow = (const float4*)(g_attn + b * 60);
        float s0 = 0.f, s1 = 0.f, s2 = 0.f, s3 = 0.f;
#pragma unroll
        for (int k = 0; k < 15; k++) {
            float4 w4 = wrow[k];
            float4 a4 = arow[k];
            s0 = fmaf(a4.x, w4.x, s0);
            s1 = fmaf(a4.y, w4.y, s1);
            s2 = fmaf(a4.z, w4.z, s2);
            s3 = fmaf(a4.w, w4.w, s3);
        }
        newH = g_H[b * 30 + lane] + ((s0 + s1) + (s2 + s3));
    }
    __syncwarp();

    int f0 = 3 * lane, f1 = f0 + 1, f2 = f0 + 2;
    float in0 = __shfl_sync(0xffffffffu, newH, (3 * (f0 % 10) + f0 / 10) & 31);
    float in1 = __shfl_sync(0xffffffffu, newH, (3 * (f1 % 10) + f1 / 10) & 31);
    float in2 = __shfl_sync(0xffffffffu, newH, (3 * (f2 % 10) + f2 / 10) & 31);
    if (lane >= 10) { in0 = 0.f; in1 = 0.f; in2 = 0.f; }
    int t = (lane < 10) ? lane : 0;
    float E[3];
    run3(in0, in1, in2, g_mats + (600 + (lay * 10 + t) * 12) * 4, E);

    float h0 = __shfl_sync(0xffffffffu, newH, (3 * lane) & 31);
    float h1 = __shfl_sync(0xffffffffu, newH, (3 * lane + 1) & 31);
    float h2 = __shfl_sync(0xffffffffu, newH, (3 * lane + 2) & 31);
    if (lane < 10) {
        g_H[b * 30 + 3 * lane + 0] = h0 + E[0];
        g_H[b * 30 + 3 * lane + 1] = h1 + E[1];
        g_H[b * 30 + 3 * lane + 2] = h2 + E[2];
    }
}

// layer-1: W_O dot + residual + FFN + reduce + classification -> out
__device__ void tail_cls(int b, int lane, const float* __restrict__ W_O,
                         const float* __restrict__ Wc, const float* __restrict__ bc,
                         float* __restrict__ out) {
    const int lay = 1;
    float newH = 0.f;
    if (lane < 30) {
        const float4* wrow = (const float4*)(W_O + (lay * 30 + lane) * 60);
        const float4* arow = (const float4*)(g_attn + b * 60);
        float s0 = 0.f, s1 = 0.f, s2 = 0.f, s3 = 0.f;
#pragma unroll
        for (int k = 0; k < 15; k++) {
            float4 w4 = wrow[k];
            float4 a4 = arow[k];
            s0 = fmaf(a4.x, w4.x, s0);
            s1 = fmaf(a4.y, w4.y, s1);
            s2 = fmaf(a4.z, w4.z, s2);
            s3 = fmaf(a4.w, w4.w, s3);
        }
        newH = g_H[b * 30 + lane] + ((s0 + s1) + (s2 + s3));
    }
    __syncwarp();

    int f0 = 3 * lane, f1 = f0 + 1, f2 = f0 + 2;
    float in0 = __shfl_sync(0xffffffffu, newH, (3 * (f0 % 10) + f0 / 10) & 31);
    float in1 = __shfl_sync(0xffffffffu, newH, (3 * (f1 % 10) + f1 / 10) & 31);
    float in2 = __shfl_sync(0xffffffffu, newH, (3 * (f2 % 10) + f2 / 10) & 31);
    if (lane >= 10) { in0 = 0.f; in1 = 0.f; in2 = 0.f; }
    int t = (lane < 10) ? lane : 0;
    float E[3];
    run3(in0, in1, in2, g_mats + (600 + (lay * 10 + t) * 12) * 4, E);

    float h0 = __shfl_sync(0xffffffffu, newH, (3 * lane) & 31);
    float h1 = __shfl_sync(0xffffffffu, newH, (3 * lane + 1) & 31);
    float h2 = __shfl_sync(0xffffffffu, newH, (3 * lane + 2) & 31);

    float red = 0.f;
    {
        float hv0 = h0 + E[0], hv1 = h1 + E[1], hv2 = h2 + E[2];
        float R[3];
        run3(hv0, hv1, hv2, g_mats + (840 + t * 12) * 4, R);
        if (lane < 10) red = R[0];
    }
    float rv[10];
#pragma unroll
    for (int tt = 0; tt < 10; tt++)
        rv[tt] = __shfl_sync(0xffffffffu, red, tt);
    if (lane < 10) {
        float s = bc[lane];
#pragma unroll
        for (int tt = 0; tt < 10; tt++) s = fmaf(rv[tt], Wc[lane * 10 + tt], s);
        out[b * 10 + lane] = s;
    }
}

// ================= prep: Rot matrices + counter reset =================
__global__ void prep_kernel(const float* __restrict__ t_stem,
                            const float* __restrict__ t_attn,
                            const float* __restrict__ t_ffn,
                            const float* __restrict__ t_red) {
    int i = blockIdx.x * blockDim.x + threadIdx.x;   // 1024 threads
    g_cnt[0][i] = 0;
    g_cnt[1][i] = 0;
    if (i < 960) {
        const float* a;
        if (i < 120)      a = t_stem + i * 3;
        else if (i < 600) a = t_attn + (i - 120) * 3;
        else if (i < 840) a = t_ffn  + (i - 600) * 3;
        else              a = t_red  + (i - 840) * 3;
        float phi = a[0], th = a[1], om = a[2];
        float c, s, cp, sp, cm, sm;
        sincosf(0.5f * th, &s, &c);
        sincosf(0.5f * (phi + om), &sp, &cp);
        sincosf(0.5f * (phi - om), &sm, &cm);
        float2* m = &g_mats[i * 4];
        m[0] = make_float2( cp * c, -sp * c);
        m[1] = make_float2(-cm * s, -sm * s);
        m[2] = make_float2( cm * s, -sm * s);
        m[3] = make_float2( cp * c,  sp * c);
    }
}

// ============ stem (half batch, smem-staged mats) ============
__global__ void stem_kernel(const float* __restrict__ x, int boff) {
    __shared__ float2 Ms[48];
    int tid = threadIdx.x;
    int t = blockIdx.x >> 1;             // 2 blocks per token, 256 thr each
    if (tid < 48) Ms[tid] = g_mats[t * 48 + tid];
    __syncthreads();

    int i = blockIdx.x * blockDim.x + tid;
    int b = boff + (i & 511);
    float E[3];
    run3(x[b * 30 + 3 * t], x[b * 30 + 3 * t + 1], x[b * 30 + 3 * t + 2], Ms, E);
#pragma unroll
    for (int k = 0; k < 3; k++) g_H[b * 30 + 3 * t + k] = E[k];
}

// ========== attention (half batch) with device-side epilogue fusion ==========
__global__ void __launch_bounds__(128) attn_kernel(int lay, int boff,
                                                   const float* __restrict__ W_O,
                                                   const float* __restrict__ Wc,
                                                   const float* __restrict__ bc,
                                                   float* __restrict__ out) {
    const int wid  = blockIdx.x * 4 + (threadIdx.x >> 5);   // [0, 3072)
    const int lane = threadIdx.x & 31;
    const int b  = boff + (wid & 511);
    const int hg = wid >> 9;                                 // [0, 6)
    const int h  = hg / 3, g = hg % 3;
    const float2* gm = g_mats + (120 + ((lay * 2 + h) * 3 + g) * 40) * 4;

    // ---- init: product state of V_q|0>, V_q = Rot(layer0,q) * RY(x_q) ----
    float2 va, vb;
    {
        int q = (lane < NT) ? lane : 0;
        float ang = (lane < NT) ? g_H[b * 30 + 3 * lane + g] : 0.f;
        float c, s;
        __sincosf(0.5f * ang, &s, &c);
        float2 g00 = gm[q * 4 + 0];
        float2 g01 = gm[q * 4 + 1];
        va = make_float2( g00.x * c + g01.x * s,  g00.y * c + g01.y * s);
        vb = make_float2(-g01.x * c + g00.x * s,  g01.y * c - g00.y * s);
    }
    float2 fa[NT], fb[NT];
    gather_factors<0>(fa, fb, va, vb);
    float2 lf = (lane & 1) ? fb[5] : fa[5];
#pragma unroll
    for (int p = 6; p < NT; p++)
        lf = cmulf(lf, ((lane >> (p - 5)) & 1) ? fb[p] : fa[p]);
    float2 T[16];
    T[0] = cmulf(lf, fa[0]);
    T[1] = cmulf(lf, fb[0]);
#pragma unroll
    for (int k = 1; k < 4; k++) {
#pragma unroll
        for (int j = 0; j < 8; j++) {
            if (j < (1 << k)) {
                T[j | (1 << k)] = cmulf(T[j], fb[k]);
                T[j]            = cmulf(T[j], fa[k]);
            }
        }
    }
    u64 re[16], im[16];
    {
        constexpr u64 SGN = 0x8000000080000000ull;
        u64 FRe  = pack2(fa[4].x, fb[4].x);
        u64 FIm  = pack2(fa[4].y, fb[4].y);
        u64 FImN = FIm ^ SGN;
#pragma unroll
        for (int j = 0; j < 16; j++) {
            u64 XX = pack2(T[j].x, T[j].x);
            u64 YY = pack2(T[j].y, T[j].y);
            re[j] = f2fma(XX, FRe, f2mul(YY, FImN));
            im[j] = f2fma(XX, FIm, f2mul(YY, FRe));
        }
    }

    run_gates<0>(re, im, gm, lane);

    u64 pp[16];
#pragma unroll
    for (int j = 0; j < 16; j++)
        pp[j] = f2fma(re[j], re[j], f2mul(im[j], im[j]));
    {
        u64 ONE = pack2(1.f, 1.f);
        u64 NEG = pack2(-1.f, -1.f);
        fwht_p<0>(pp, ONE, NEG);
    }
    float res[NT];
    meas_from_p<0>(pp, res, lane);
#pragma unroll
    for (int w = 0; w < NT; w++) {
#pragma unroll
        for (int off = 16; off; off >>= 1)
            res[w] += __shfl_xor_sync(0xffffffffu, res[w], off);
    }
    if (lane == 0) {
#pragma unroll
        for (int w = 0; w < NT; w++)
            g_attn[b * 60 + h * 30 + 3 * w + g] = res[w];
    }

    // ---- device-side epilogue: last warp of b runs the per-b tail ----
    __threadfence();
    int old = 0;
    if (lane == 0) old = atomicAdd(&g_cnt[lay][b], 1);
    old = __shfl_sync(0xffffffffu, old, 0);
    if (old == 5) {
        __threadfence();   // acquire: see all 6 warps' g_attn writes
        if (lay == 0) tail_wo_ffn(b, lane, W_O);
        else          tail_cls(b, lane, W_O, Wc, bc, out);
    }
}

// ================= launch: 2-stream pipeline, fused epilogues =================
extern "C" void kernel_launch(void* const* d_in, const int* in_sizes, int n_in,
                              void* d_out, int out_size) {
    const float* x_      = (const float*)d_in[0];
    const float* t_stem  = (const float*)d_in[1];
    const float* t_attn  = (const float*)d_in[2];
    const float* W_O     = (const float*)d_in[3];
    const float* t_ffn   = (const float*)d_in[4];
    const float* t_red   = (const float*)d_in[5];
    const float* W_cls   = (const float*)d_in[6];
    const float* b_cls   = (const float*)d_in[7];
    float* out = (float*)d_out;

    static cudaStream_t s1 = nullptr;
    static cudaEvent_t  ef = nullptr, ej = nullptr;
    if (s1 == nullptr) {
        cudaStreamCreateWithFlags(&s1, cudaStreamNonBlocking);
        cudaEventCreateWithFlags(&ef, cudaEventDisableTiming);
        cudaEventCreateWithFlags(&ej, cudaEventDisableTiming);
    }

    prep_kernel<<<4, 256>>>(t_stem, t_attn, t_ffn, t_red);

    cudaEventRecord(ef, 0);
    cudaStreamWaitEvent(s1, ef, 0);

    // half A on default stream
    stem_kernel<<<20, 256>>>(x_, 0);
    attn_kernel<<<768, 128>>>(0, 0, W_O, W_cls, b_cls, out);
    attn_kernel<<<768, 128>>>(1, 0, W_O, W_cls, b_cls, out);

    // half B on s1
    stem_kernel<<<20, 256, 0, s1>>>(x_, HALF);
    attn_kernel<<<768, 128, 0, s1>>>(0, HALF, W_O, W_cls, b_cls, out);
    attn_kernel<<<768, 128, 0, s1>>>(1, HALF, W_O, W_cls, b_cls, out);

    cudaEventRecord(ej, s1);
    cudaStreamWaitEvent(0, ej, 0);
}

// round 15
// speedup vs baseline: 1.0691x; 1.0691x over previous
#include <cuda_runtime.h>
#include <math.h>

#define BATCH   1024
#define HALF    512
#define NT      10
#define PADDED  30
#define DEPTH   4
#define LAYERS  2
#define NHEADS  2
#define NCLS    10

typedef unsigned long long u64;

// g_mats layout (each matrix = 4 float2, row-major 2x2):
//   stem   : [0,120)    (t*4+l)*3+w      (unused by stem kernel now, kept for layout)
//   attn   : [120,600)  (((lay*2+h)*3+g)*4+l)*10+w
//   ffn    : [600,840)  ((lay*10+t)*4+l)*3+w
//   reduce : [840,960)  (t*4+l)*3+w
__device__ float2 g_mats[960 * 4];
__device__ float  g_H[BATCH * PADDED];
__device__ float  g_attn[BATCH * PADDED * NHEADS];

// ================= compile-time GF(2) mask tables =================
__host__ __device__ constexpr int parity(unsigned x) {
    int p = 0; while (x) { p ^= (int)(x & 1u); x >>= 1; } return p;
}

struct Masks {
    unsigned pm[DEPTH][NT];
    unsigned am[DEPTH][NT];
    unsigned zm[NT];
};

__host__ __device__ constexpr Masks make_masks() {
    Masks M{};
    for (int l = 0; l < DEPTH; l++) {
        unsigned R[NT]{}, Ri[NT]{};
        for (int u = 0; u < NT; u++) { R[u] = 1u << u; Ri[u] = 1u << u; }
        for (int ll = 0; ll < l; ll++) {
            int r = ll + 1;
            for (int i = 0; i < NT; i++) R[(i + r) % NT] ^= R[i];
        }
        for (int ll = l - 1; ll >= 0; ll--) {
            int r = ll + 1;
            for (int i = NT - 1; i >= 0; i--) Ri[(i + r) % NT] ^= Ri[i];
        }
        for (int w = 0; w < NT; w++) {
            unsigned m = 0;
            for (int u = 0; u < NT; u++) if ((Ri[u] >> w) & 1u) m |= 1u << u;
            M.pm[l][w] = m;
            M.am[l][w] = R[w];
        }
    }
    unsigned R[NT]{};
    for (int u = 0; u < NT; u++) R[u] = 1u << u;
    for (int ll = 0; ll < DEPTH; ll++) {
        int r = ll + 1;
        for (int i = 0; i < NT; i++) R[(i + r) % NT] ^= R[i];
    }
    for (int w = 0; w < NT; w++) M.zm[w] = R[w];
    return M;
}

struct Masks2 {
    unsigned pm[3][NT];
    unsigned am[3][NT];
    unsigned zm[NT];
    int posq[NT];
};

__host__ __device__ constexpr Masks2 make_masks2() {
    Masks M = make_masks();
    unsigned bestS = 0x1Fu; int bestScore = -1;
    for (unsigned S = 0; S < 1024u; S++) {
        int pc = 0;
        for (int q = 0; q < NT; q++) pc += (int)((S >> q) & 1u);
        if (pc != 5) continue;
        int score = 0;
        for (int l = 1; l < DEPTH; l++)
            for (int w = 0; w < NT; w++)
                if ((M.pm[l][w] & ~S & 0x3FFu) == 0u) score++;
        if (score > bestScore) { bestScore = score; bestS = S; }
    }
    int qpos[NT]{};
    Masks2 R{};
    {
        int lp = 0, hp = 5;
        for (int q = 0; q < NT; q++) {
            int p = ((bestS >> q) & 1u) ? lp++ : hp++;
            qpos[q] = p;
        }
        for (int q = 0; q < NT; q++) R.posq[qpos[q]] = q;
    }
    for (int l = 1; l < DEPTH; l++)
        for (int w = 0; w < NT; w++) {
            unsigned pm2 = 0, am2 = 0;
            for (int q = 0; q < NT; q++) {
                if ((M.pm[l][w] >> q) & 1u) pm2 |= 1u << qpos[q];
                if ((M.am[l][w] >> q) & 1u) am2 |= 1u << qpos[q];
            }
            R.pm[l - 1][w] = pm2;
            R.am[l - 1][w] = am2;
        }
    for (int w = 0; w < NT; w++) {
        unsigned z2 = 0;
        for (int q = 0; q < NT; q++) if ((M.zm[w] >> q) & 1u) z2 |= 1u << qpos[q];
        R.zm[w] = z2;
    }
    return R;
}
constexpr Masks2 MK2 = make_masks2();

// ================= packed f32x2 helpers =================
__device__ __forceinline__ u64 pack2(float lo, float hi) {
    u64 r; asm("mov.b64 %0, {%1,%2};" : "=l"(r) : "f"(lo), "f"(hi)); return r;
}
__device__ __forceinline__ float2 unpack2(u64 a) {
    float2 f; asm("mov.b64 {%0,%1}, %2;" : "=f"(f.x), "=f"(f.y) : "l"(a)); return f;
}
__device__ __forceinline__ u64 swap2(u64 a) {
    u64 r; asm("{ .reg .b32 lo, hi; mov.b64 {lo,hi}, %1; mov.b64 %0, {hi,lo}; }" : "=l"(r) : "l"(a)); return r;
}
__device__ __forceinline__ u64 f2fma(u64 a, u64 b, u64 c) {
    u64 r; asm("fma.rn.f32x2 %0, %1, %2, %3;" : "=l"(r) : "l"(a), "l"(b), "l"(c)); return r;
}
__device__ __forceinline__ u64 f2mul(u64 a, u64 b) {
    u64 r; asm("mul.rn.f32x2 %0, %1, %2;" : "=l"(r) : "l"(a), "l"(b)); return r;
}
__device__ __forceinline__ u64 shfl64_xor(u64 v, int m) {
    unsigned lo = (unsigned)v, hi = (unsigned)(v >> 32);
    lo = __shfl_xor_sync(0xffffffffu, lo, m);
    hi = __shfl_xor_sync(0xffffffffu, hi, m);
    return ((u64)hi << 32) | lo;
}

__device__ __forceinline__ float2 cmulf(float2 a, float2 b) {
    return make_float2(a.x * b.x - a.y * b.y, a.x * b.y + a.y * b.x);
}

// ================= SoA butterfly =================
__device__ __forceinline__ void soa_bfly(u64 xr, u64 xi, u64 yr, u64 yi,
                                         u64 CX, u64 cyp, u64 cyq, u64 dxp,
                                         u64 DYRE, u64 DYIM, u64& nr, u64& ni) {
    nr = f2fma(CX, xr, f2fma(cyp, xi, f2fma(dxp, yr, f2mul(DYRE, yi))));
    ni = f2fma(CX, xi, f2fma(cyq, xr, f2fma(dxp, yi, f2mul(DYIM, yr))));
}

// Case A: pure local, bit4 not in pair mask
template<unsigned MLO4, unsigned ALO4, int J>
__device__ __forceinline__ void loopA(u64* re, u64* im, u64 CX, u64 cy0, u64 cy1,
                                      u64 dx0, u64 dx1, u64 DYRE, u64 DYIM) {
    if constexpr (J < 16) {
        constexpr unsigned LOW = MLO4 & (0u - MLO4);
        if constexpr ((J & (int)LOW) == 0) {
            constexpr int J2 = J ^ (int)MLO4;
            constexpr int P  = parity(ALO4 & (unsigned)J);
            constexpr int P2 = parity(ALO4 & (unsigned)J2);
            u64 ar = re[J], ai = im[J], br = re[J2], bi = im[J2];
            u64 nr1, ni1, nr2, ni2;
            soa_bfly(ar, ai, br, bi, CX, P  ? cy1 : cy0, P  ? cy0 : cy1, P  ? dx1 : dx0, DYRE, DYIM, nr1, ni1);
            soa_bfly(br, bi, ar, ai, CX, P2 ? cy1 : cy0, P2 ? cy0 : cy1, P2 ? dx1 : dx0, DYRE, DYIM, nr2, ni2);
            re[J] = nr1; im[J] = ni1; re[J2] = nr2; im[J2] = ni2;
        }
        loopA<MLO4, ALO4, J + 1>(re, im, CX, cy0, cy1, dx0, dx1, DYRE, DYIM);
    }
}

// Case B: pair mask == bit4 only
template<unsigned ALO4, int J>
__device__ __forceinline__ void loopB(u64* re, u64* im, u64 CX, u64 cy0, u64 cy1,
                                      u64 dx0, u64 dx1, u64 DYRE, u64 DYIM) {
    if constexpr (J < 16) {
        constexpr int P = parity(ALO4 & (unsigned)J);
        u64 yr = swap2(re[J]), yi = swap2(im[J]);
        u64 nr, ni;
        soa_bfly(re[J], im[J], yr, yi, CX, P ? cy1 : cy0, P ? cy0 : cy1, P ? dx1 : dx0, DYRE, DYIM, nr, ni);
        re[J] = nr; im[J] = ni;
        loopB<ALO4, J + 1>(re, im, CX, cy0, cy1, dx0, dx1, DYRE, DYIM);
    }
}

// Case C: local with bit4 + low bits
template<unsigned MLO4, unsigned ALO4, int J>
__device__ __forceinline__ void loopC(u64* re, u64* im, u64 CX, u64 cy0, u64 cy1,
                                      u64 dx0, u64 dx1, u64 DYRE, u64 DYIM) {
    if constexpr (J < 16) {
        constexpr unsigned LOW = MLO4 & (0u - MLO4);
        if constexpr ((J & (int)LOW) == 0) {
            constexpr int J2 = J ^ (int)MLO4;
            constexpr int P  = parity(ALO4 & (unsigned)J);
            constexpr int P2 = parity(ALO4 & (unsigned)J2);
            u64 y1r = swap2(re[J2]), y1i = swap2(im[J2]);
            u64 y2r = swap2(re[J]),  y2i = swap2(im[J]);
            u64 nr1, ni1, nr2, ni2;
            soa_bfly(re[J],  im[J],  y1r, y1i, CX, P  ? cy1 : cy0, P  ? cy0 : cy1, P  ? dx1 : dx0, DYRE, DYIM, nr1, ni1);
            soa_bfly(re[J2], im[J2], y2r, y2i, CX, P2 ? cy1 : cy0, P2 ? cy0 : cy1, P2 ? dx1 : dx0, DYRE, DYIM, nr2, ni2);
            re[J] = nr1; im[J] = ni1; re[J2] = nr2; im[J2] = ni2;
        }
        loopC<MLO4, ALO4, J + 1>(re, im, CX, cy0, cy1, dx0, dx1, DYRE, DYIM);
    }
}

// Case D: lane bits only
template<unsigned MHI, unsigned MB4, unsigned ALO4, int J>
__device__ __forceinline__ void loopD(u64* re, u64* im, u64 CX, u64 cy0, u64 cy1,
                                      u64 dx0, u64 dx1, u64 DYRE, u64 DYIM) {
    if constexpr (J < 16) {
        constexpr int P = parity(ALO4 & (unsigned)J);
        u64 yr = shfl64_xor(re[J], (int)MHI);
        u64 yi = shfl64_xor(im[J], (int)MHI);
        if constexpr (MB4) { yr = swap2(yr); yi = swap2(yi); }
        u64 nr, ni;
        soa_bfly(re[J], im[J], yr, yi, CX, P ? cy1 : cy0, P ? cy0 : cy1, P ? dx1 : dx0, DYRE, DYIM, nr, ni);
        re[J] = nr; im[J] = ni;
        loopD<MHI, MB4, ALO4, J + 1>(re, im, CX, cy0, cy1, dx0, dx1, DYRE, DYIM);
    }
}

// Case F: lane + local bits
template<unsigned MLO4, unsigned MB4, unsigned MHI, unsigned ALO4, int J>
__device__ __forceinline__ void loopF(u64* re, u64* im, u64 CX, u64 cy0, u64 cy1,
                                      u64 dx0, u64 dx1, u64 DYRE, u64 DYIM) {
    if constexpr (J < 16) {
        constexpr unsigned LOW = MLO4 & (0u - MLO4);
        if constexpr ((J & (int)LOW) == 0) {
            constexpr int J2 = J ^ (int)MLO4;
            constexpr int P  = parity(ALO4 & (unsigned)J);
            constexpr int P2 = parity(ALO4 & (unsigned)J2);
            u64 y1r = shfl64_xor(re[J2], (int)MHI);
            u64 y1i = shfl64_xor(im[J2], (int)MHI);
            u64 y2r = shfl64_xor(re[J],  (int)MHI);
            u64 y2i = shfl64_xor(im[J],  (int)MHI);
            if constexpr (MB4) {
                y1r = swap2(y1r); y1i = swap2(y1i);
                y2r = swap2(y2r); y2i = swap2(y2i);
            }
            u64 nr1, ni1, nr2, ni2;
            soa_bfly(re[J],  im[J],  y1r, y1i, CX, P  ? cy1 : cy0, P  ? cy0 : cy1, P  ? dx1 : dx0, DYRE, DYIM, nr1, ni1);
            soa_bfly(re[J2], im[J2], y2r, y2i, CX, P2 ? cy1 : cy0, P2 ? cy0 : cy1, P2 ? dx1 : dx0, DYRE, DYIM, nr2, ni2);
            re[J] = nr1; im[J] = ni1; re[J2] = nr2; im[J2] = ni2;
        }
        loopF<MLO4, MB4, MHI, ALO4, J + 1>(re, im, CX, cy0, cy1, dx0, dx1, DYRE, DYIM);
    }
}

template<int L, int W>
__device__ __forceinline__ void apply_gate(u64* re, u64* im,
                                           const float2* __restrict__ gm, int lane) {
    constexpr unsigned m    = MK2.pm[L][W];
    constexpr unsigned a    = MK2.am[L][W];
    constexpr unsigned mlo4 = m & 15u;
    constexpr unsigned mb4  = (m >> 4) & 1u;
    constexpr unsigned mhi  = (m >> 5) & 31u;
    constexpr unsigned alo4 = a & 15u;
    constexpr unsigned ab4  = (a >> 4) & 1u;
    constexpr unsigned ahi  = (a >> 5) & 31u;
    float2 g00 = gm[((L + 1) * 10 + W) * 4 + 0];
    float2 g01 = gm[((L + 1) * 10 + W) * 4 + 1];
    float cx = g00.x, cy = g00.y, dx = g01.x, dy = g01.y;
    u64 CX   = pack2(cx, cx);
    u64 CY0  = pack2(-cy, ab4 ? cy : -cy);
    u64 DX0  = pack2(dx, ab4 ? -dx : dx);
    u64 DYRE = pack2(-dy, -dy);
    u64 DYIM = pack2(dy, dy);
    constexpr u64 SGN = 0x8000000080000000ull;
    u64 CY1 = CY0 ^ SGN;
    u64 DX1 = DX0 ^ SGN;
    int plane = (int)(__popc(ahi & (unsigned)lane) & 1);
    u64 cy0 = plane ? CY1 : CY0, cy1 = plane ? CY0 : CY1;
    u64 dx0 = plane ? DX1 : DX0, dx1 = plane ? DX0 : DX1;
    if constexpr (mhi == 0u && mb4 == 0u) {
        loopA<mlo4, alo4, 0>(re, im, CX, cy0, cy1, dx0, dx1, DYRE, DYIM);
    } else if constexpr (mhi == 0u && mlo4 == 0u) {
        loopB<alo4, 0>(re, im, CX, cy0, cy1, dx0, dx1, DYRE, DYIM);
    } else if constexpr (mhi == 0u) {
        loopC<mlo4, alo4, 0>(re, im, CX, cy0, cy1, dx0, dx1, DYRE, DYIM);
    } else if constexpr (mlo4 == 0u) {
        loopD<mhi, mb4, alo4, 0>(re, im, CX, cy0, cy1, dx0, dx1, DYRE, DYIM);
    } else {
        loopF<mlo4, mb4, mhi, alo4, 0>(re, im, CX, cy0, cy1, dx0, dx1, DYRE, DYIM);
    }
}

template<int G>
__device__ __forceinline__ void run_gates(u64* re, u64* im,
                                          const float2* __restrict__ gm, int lane) {
    if constexpr (G < 3 * NT) {
        apply_gate<G / NT, G % NT>(re, im, gm, lane);
        run_gates<G + 1>(re, im, gm, lane);
    }
}

// ================= measurement: packed |amp|^2 + packed FWHT =================
template<int K, int J>
__device__ __forceinline__ void fwht_stage_p(u64* pp, u64 ONE, u64 NEG) {
    if constexpr (J < 16) {
        if constexpr ((J & (1 << K)) == 0) {
            constexpr int J2 = J | (1 << K);
            u64 a = pp[J], b = pp[J2];
            pp[J]  = f2fma(ONE, b, a);
            pp[J2] = f2fma(NEG, b, a);
        }
        fwht_stage_p<K, J + 1>(pp, ONE, NEG);
    }
}
template<int K>
__device__ __forceinline__ void fwht_p(u64* pp, u64 ONE, u64 NEG) {
    if constexpr (K < 4) {
        fwht_stage_p<K, 0>(pp, ONE, NEG);
        fwht_p<K + 1>(pp, ONE, NEG);
    }
}
template<int W>
__device__ __forceinline__ void meas_from_p(const u64* pp, float* res, int lane) {
    if constexpr (W < NT) {
        constexpr unsigned z   = MK2.zm[W];
        constexpr unsigned idx = z & 15u;
        constexpr unsigned b4  = (z >> 4) & 1u;
        constexpr unsigned zhi = (z >> 5) & 31u;
        float2 v = unpack2(pp[idx]);
        float acc = b4 ? (v.x - v.y) : (v.x + v.y);
        if ((int)(__popc(zhi & (unsigned)lane) & 1)) acc = -acc;
        res[W] = acc;
        meas_from_p<W + 1>(pp, res, lane);
    }
}

// compile-time posq gather of embedding factors into position order
template<int P>
__device__ __forceinline__ void gather_factors(float2* fa, float2* fb, float2 va, float2 vb) {
    if constexpr (P < NT) {
        constexpr int q = MK2.posq[P];
        fa[P].x = __shfl_sync(0xffffffffu, va.x, q);
        fa[P].y = __shfl_sync(0xffffffffu, va.y, q);
        fb[P].x = __shfl_sync(0xffffffffu, vb.x, q);
        fb[P].y = __shfl_sync(0xffffffffu, vb.y, q);
        gather_factors<P + 1>(fa, fb, va, vb);
    }
}

// ================= 3-qubit register circuit (matrices from smem) =============
__device__ __forceinline__ float2 cadd3(float2 a, float2 b) {
    return make_float2(a.x + b.x, a.y + b.y);
}
__device__ __forceinline__ void run3(float x0, float x1, float x2,
                                     const float2* M, float E[3]) {
    float c[3], s[3];
    __sincosf(0.5f * x0, &s[0], &c[0]);
    __sincosf(0.5f * x1, &s[1], &c[1]);
    __sincosf(0.5f * x2, &s[2], &c[2]);
    float2 a[8];
#pragma unroll
    for (int i = 0; i < 8; i++) {
        float v = ((i >> 2) & 1 ? s[0] : c[0]) *
                  ((i >> 1) & 1 ? s[1] : c[1]) *
                  ((i      ) & 1 ? s[2] : c[2]);
        a[i] = make_float2(v, 0.f);
    }
#pragma unroll
    for (int l = 0; l < 4; l++) {
#pragma unroll
        for (int w = 0; w < 3; w++) {
            const float2* m = M + (l * 3 + w) * 4;
            const int p = 2 - w;
#pragma unroll
            for (int i0 = 0; i0 < 8; i0++) {
                if (i0 & (1 << p)) continue;
                int i1 = i0 | (1 << p);
                float2 A = a[i0], B = a[i1];
                a[i0] = cadd3(cmulf(m[0], A), cmulf(m[1], B));
                a[i1] = cadd3(cmulf(m[2], A), cmulf(m[3], B));
            }
        }
        const int r = (l & 1) + 1;
#pragma unroll
        for (int i = 0; i < 3; i++) {
            int pc = 2 - i;
            int pt = 2 - ((i + r) % 3);
#pragma unroll
            for (int idx = 0; idx < 8; idx++) {
                if (((idx >> pc) & 1) && !((idx >> pt) & 1)) {
                    int j = idx | (1 << pt);
                    float2 t = a[idx]; a[idx] = a[j]; a[j] = t;
                }
            }
        }
    }
    E[0] = E[1] = E[2] = 0.f;
#pragma unroll
    for (int i = 0; i < 8; i++) {
        float p = a[i].x * a[i].x + a[i].y * a[i].y;
        E[0] += (i & 4) ? -p : p;
        E[1] += (i & 2) ? -p : p;
        E[2] += (i & 1) ? -p : p;
    }
}

// rot matrix from 3 angles -> 4 float2 (row-major 2x2)
__device__ __forceinline__ void make_rot(float phi, float th, float om, float2* m) {
    float c, s, cp, sp, cm, sm;
    __sincosf(0.5f * th, &s, &c);
    __sincosf(0.5f * (phi + om), &sp, &cp);
    __sincosf(0.5f * (phi - om), &sm, &cm);
    m[0] = make_float2( cp * c, -sp * c);
    m[1] = make_float2(-cm * s, -sm * s);
    m[2] = make_float2( cm * s, -sm * s);
    m[3] = make_float2( cp * c,  sp * c);
}

// ================= prep: attn/ffn/reduce Rot matrices (no stem dep) ==========
__global__ void prep_kernel(const float* __restrict__ t_attn,
                            const float* __restrict__ t_ffn,
                            const float* __restrict__ t_red) {
    int i = blockIdx.x * blockDim.x + threadIdx.x;   // [0, 1024)
    if (i >= 120 && i < 960) {
        const float* a;
        if (i < 600)      a = t_attn + (i - 120) * 3;
        else if (i < 840) a = t_ffn  + (i - 600) * 3;
        else              a = t_red  + (i - 840) * 3;
        float phi = a[0], th = a[1], om = a[2];
        float c, s, cp, sp, cm, sm;
        sincosf(0.5f * th, &s, &c);
        sincosf(0.5f * (phi + om), &sp, &cp);
        sincosf(0.5f * (phi - om), &sm, &cm);
        float2* m = &g_mats[i * 4];
        m[0] = make_float2( cp * c, -sp * c);
        m[1] = make_float2(-cm * s, -sm * s);
        m[2] = make_float2( cm * s, -sm * s);
        m[3] = make_float2( cp * c,  sp * c);
    }
}

// ====== stem (half batch): self-contained, builds its own matrices ===========
__global__ void stem_kernel(const float* __restrict__ x,
                            const float* __restrict__ t_stem, int boff) {
    __shared__ float2 Ms[48];            // this token's 12 matrices
    int tid = threadIdx.x;
    int t = blockIdx.x >> 1;             // 2 blocks per token, 256 thr each
    if (tid < 12) {
        const float* a = t_stem + (t * 12 + tid) * 3;  // (t*4+l)*3+w == t*12 + (l*3+w)
        make_rot(a[0], a[1], a[2], &Ms[tid * 4]);
    }
    __syncthreads();

    int i = blockIdx.x * blockDim.x + tid;
    int b = boff + (i & 511);
    float E[3];
    run3(x[b * 30 + 3 * t], x[b * 30 + 3 * t + 1], x[b * 30 + 3 * t + 2], Ms, E);
#pragma unroll
    for (int k = 0; k < 3; k++) g_H[b * 30 + 3 * t + k] = E[k];
}

// ================= attention (half batch) =================
__global__ void __launch_bounds__(128) attn_kernel(int lay, int boff) {
    const int wid  = blockIdx.x * 4 + (threadIdx.x >> 5);   // [0, 3072)
    const int lane = threadIdx.x & 31;
    const int b  = boff + (wid & 511);
    const int hg = wid >> 9;                                 // [0, 6)
    const int h  = hg / 3, g = hg % 3;
    const float2* gm = g_mats + (120 + ((lay * 2 + h) * 3 + g) * 40) * 4;

    // ---- init: product state of V_q|0>, V_q = Rot(layer0,q) * RY(x_q) ----
    float2 va, vb;
    {
        int q = (lane < NT) ? lane : 0;
        float ang = (lane < NT) ? g_H[b * 30 + 3 * lane + g] : 0.f;
        float c, s;
        __sincosf(0.5f * ang, &s, &c);
        float2 g00 = gm[q * 4 + 0];
        float2 g01 = gm[q * 4 + 1];
        va = make_float2( g00.x * c + g01.x * s,  g00.y * c + g01.y * s);
        vb = make_float2(-g01.x * c + g00.x * s,  g01.y * c - g00.y * s);
    }
    float2 fa[NT], fb[NT];
    gather_factors<0>(fa, fb, va, vb);
    float2 lf = (lane & 1) ? fb[5] : fa[5];
#pragma unroll
    for (int p = 6; p < NT; p++)
        lf = cmulf(lf, ((lane >> (p - 5)) & 1) ? fb[p] : fa[p]);
    float2 T[16];
    T[0] = cmulf(lf, fa[0]);
    T[1] = cmulf(lf, fb[0]);
#pragma unroll
    for (int k = 1; k < 4; k++) {
#pragma unroll
        for (int j = 0; j < 8; j++) {
            if (j < (1 << k)) {
                T[j | (1 << k)] = cmulf(T[j], fb[k]);
                T[j]            = cmulf(T[j], fa[k]);
            }
        }
    }
    u64 re[16], im[16];
    {
        constexpr u64 SGN = 0x8000000080000000ull;
        u64 FRe  = pack2(fa[4].x, fb[4].x);
        u64 FIm  = pack2(fa[4].y, fb[4].y);
        u64 FImN = FIm ^ SGN;
#pragma unroll
        for (int j = 0; j < 16; j++) {
            u64 XX = pack2(T[j].x, T[j].x);
            u64 YY = pack2(T[j].y, T[j].y);
            re[j] = f2fma(XX, FRe, f2mul(YY, FImN));
            im[j] = f2fma(XX, FIm, f2mul(YY, FRe));
        }
    }

    run_gates<0>(re, im, gm, lane);

    u64 pp[16];
#pragma unroll
    for (int j = 0; j < 16; j++)
        pp[j] = f2fma(re[j], re[j], f2mul(im[j], im[j]));
    {
        u64 ONE = pack2(1.f, 1.f);
        u64 NEG = pack2(-1.f, -1.f);
        fwht_p<0>(pp, ONE, NEG);
    }
    float res[NT];
    meas_from_p<0>(pp, res, lane);
#pragma unroll
    for (int w = 0; w < NT; w++) {
#pragma unroll
        for (int off = 16; off; off >>= 1)
            res[w] += __shfl_xor_sync(0xffffffffu, res[w], off);
    }
    if (lane == 0) {
#pragma unroll
        for (int w = 0; w < NT; w++)
            g_attn[b * 60 + h * 30 + 3 * w + g] = res[w];
    }
}

// ====== fused W_O + residual + FFN (layer 0, half batch, smem-staged) ========
__global__ void wo_ffn_kernel(const float* __restrict__ W_O, int lay, int boff) {
    __shared__ float2 Ms[480];
    int tid = threadIdx.x;
    {
        const float4* src = (const float4*)(g_mats + (600 + lay * 120) * 4);
        float4* dst = (float4*)Ms;
        if (tid < 240) dst[tid] = src[tid];
    }
    __syncthreads();

    int gt = blockIdx.x * blockDim.x + tid;
    int b = boff + (gt >> 5), lane = gt & 31;

    float newH = 0.f;
    if (lane < 30) {
        const float4* wrow = (const float4*)(W_O + (lay * 30 + lane) * 60);
        const float4* arow = (const float4*)(g_attn + b * 60);
        float s0 = 0.f, s1 = 0.f, s2 = 0.f, s3 = 0.f;
#pragma unroll
        for (int k = 0; k < 15; k++) {
            float4 w4 = wrow[k];
            float4 a4 = arow[k];
            s0 = fmaf(a4.x, w4.x, s0);
            s1 = fmaf(a4.y, w4.y, s1);
            s2 = fmaf(a4.z, w4.z, s2);
            s3 = fmaf(a4.w, w4.w, s3);
        }
        newH = g_H[b * 30 + lane] + ((s0 + s1) + (s2 + s3));
    }
    __syncwarp();

    int f0 = 3 * lane, f1 = f0 + 1, f2 = f0 + 2;
    float in0 = __shfl_sync(0xffffffffu, newH, (3 * (f0 % 10) + f0 / 10) & 31);
    float in1 = __shfl_sync(0xffffffffu, newH, (3 * (f1 % 10) + f1 / 10) & 31);
    float in2 = __shfl_sync(0xffffffffu, newH, (3 * (f2 % 10) + f2 / 10) & 31);
    if (lane >= 10) { in0 = 0.f; in1 = 0.f; in2 = 0.f; }
    int t = (lane < 10) ? lane : 0;
    float E[3];
    run3(in0, in1, in2, Ms + t * 48, E);

    float h0 = __shfl_sync(0xffffffffu, newH, (3 * lane) & 31);
    float h1 = __shfl_sync(0xffffffffu, newH, (3 * lane + 1) & 31);
    float h2 = __shfl_sync(0xffffffffu, newH, (3 * lane + 2) & 31);
    if (lane < 10) {
        g_H[b * 30 + 3 * lane + 0] = h0 + E[0];
        g_H[b * 30 + 3 * lane + 1] = h1 + E[1];
        g_H[b * 30 + 3 * lane + 2] = h2 + E[2];
    }
}

// ===== layer-1 W_O + FFN + reduce + cls (half batch, smem-staged) ====
__global__ void wo_ffn_cls_kernel(const float* __restrict__ W_O,
                                  const float* __restrict__ Wc,
                                  const float* __restrict__ bc,
                                  float* __restrict__ out, int boff) {
    __shared__ float2 Mf[480];
    __shared__ float2 Mr[480];
    int tid = threadIdx.x;
    {
        const float4* srcf = (const float4*)(g_mats + (600 + 120) * 4);
        const float4* srcr = (const float4*)(g_mats + 840 * 4);
        float4* dstf = (float4*)Mf;
        float4* dstr = (float4*)Mr;
        if (tid < 240) { dstf[tid] = srcf[tid]; dstr[tid] = srcr[tid]; }
    }
    __syncthreads();

    int gt = blockIdx.x * blockDim.x + tid;
    int b = boff + (gt >> 5), lane = gt & 31;
    const int lay = 1;

    float newH = 0.f;
    if (lane < 30) {
        const float4* wrow = (const float4*)(W_O + (lay * 30 + lane) * 60);
        const float4* arow = (const float4*)(g_attn + b * 60);
        float s0 = 0.f, s1 = 0.f, s2 = 0.f, s3 = 0.f;
#pragma unroll
        for (int k = 0; k < 15; k++) {
            float4 w4 = wrow[k];
            float4 a4 = arow[k];
            s0 = fmaf(a4.x, w4.x, s0);
            s1 = fmaf(a4.y, w4.y, s1);
            s2 = fmaf(a4.z, w4.z, s2);
            s3 = fmaf(a4.w, w4.w, s3);
        }
        newH = g_H[b * 30 + lane] + ((s0 + s1) + (s2 + s3));
    }
    __syncwarp();

    int f0 = 3 * lane, f1 = f0 + 1, f2 = f0 + 2;
    float in0 = __shfl_sync(0xffffffffu, newH, (3 * (f0 % 10) + f0 / 10) & 31);
    float in1 = __shfl_sync(0xffffffffu, newH, (3 * (f1 % 10) + f1 / 10) & 31);
    float in2 = __shfl_sync(0xffffffffu, newH, (3 * (f2 % 10) + f2 / 10) & 31);
    if (lane >= 10) { in0 = 0.f; in1 = 0.f; in2 = 0.f; }
    int t = (lane < 10) ? lane : 0;
    float E[3];
    run3(in0, in1, in2, Mf + t * 48, E);

    float h0 = __shfl_sync(0xffffffffu, newH, (3 * lane) & 31);
    float h1 = __shfl_sync(0xffffffffu, newH, (3 * lane + 1) & 31);
    float h2 = __shfl_sync(0xffffffffu, newH, (3 * lane + 2) & 31);

    float red = 0.f;
    {
        float hv0 = h0 + E[0], hv1 = h1 + E[1], hv2 = h2 + E[2];
        float R[3];
        run3(hv0, hv1, hv2, Mr + t * 48, R);
        if (lane < 10) red = R[0];
    }
    float rv[10];
#pragma unroll
    for (int tt = 0; tt < 10; tt++)
        rv[tt] = __shfl_sync(0xffffffffu, red, tt);
    if (lane < 10) {
        float s = bc[lane];
#pragma unroll
        for (int tt = 0; tt < 10; tt++) s = fmaf(rv[tt], Wc[lane * 10 + tt], s);
        out[b * 10 + lane] = s;
    }
}

// ================= launch: 2-stream pipeline, concurrent prep =================
extern "C" void kernel_launch(void* const* d_in, const int* in_sizes, int n_in,
                              void* d_out, int out_size) {
    const float* x_      = (const float*)d_in[0];
    const float* t_stem  = (const float*)d_in[1];
    const float* t_attn  = (const float*)d_in[2];
    const float* W_O     = (const float*)d_in[3];
    const float* t_ffn   = (const float*)d_in[4];
    const float* t_red   = (const float*)d_in[5];
    const float* W_cls   = (const float*)d_in[6];
    const float* b_cls   = (const float*)d_in[7];
    float* out = (float*)d_out;

    static cudaStream_t s1 = nullptr, s2 = nullptr;
    static cudaEvent_t  ef = nullptr, ep = nullptr, ej = nullptr;
    if (s1 == nullptr) {
        cudaStreamCreateWithFlags(&s1, cudaStreamNonBlocking);
        cudaStreamCreateWithFlags(&s2, cudaStreamNonBlocking);
        cudaEventCreateWithFlags(&ef, cudaEventDisableTiming);
        cudaEventCreateWithFlags(&ep, cudaEventDisableTiming);
        cudaEventCreateWithFlags(&ej, cudaEventDisableTiming);
    }

    // fork s1/s2 off the capture-origin stream
    cudaEventRecord(ef, 0);
    cudaStreamWaitEvent(s1, ef, 0);
    cudaStreamWaitEvent(s2, ef, 0);

    // prep (attn/ffn/reduce matrices) on s2, concurrent with both stems
    prep_kernel<<<4, 256, 0, s2>>>(t_attn, t_ffn, t_red);
    cudaEventRecord(ep, s2);

    // half A on default stream: stem (self-contained) then attn chain after prep
    stem_kernel<<<20, 256>>>(x_, t_stem, 0);
    cudaStreamWaitEvent(0, ep, 0);
    attn_kernel<<<768, 128>>>(0, 0);
    wo_ffn_kernel<<<64, 256>>>(W_O, 0, 0);
    attn_kernel<<<768, 128>>>(1, 0);
    wo_ffn_cls_kernel<<<64, 256>>>(W_O, W_cls, b_cls, out, 0);

    // half B on s1
    stem_kernel<<<20, 256, 0, s1>>>(x_, t_stem, HALF);
    cudaStreamWaitEvent(s1, ep, 0);
    attn_kernel<<<768, 128, 0, s1>>>(0, HALF);
    wo_ffn_kernel<<<64, 256, 0, s1>>>(W_O, 0, HALF);
    attn_kernel<<<768, 128, 0, s1>>>(1, HALF);
    wo_ffn_cls_kernel<<<64, 256, 0, s1>>>(W_O, W_cls, b_cls, out, HALF);

    // join: default stream waits for s1
    cudaEventRecord(ej, s1);
    cudaStreamWaitEvent(0, ej, 0);
}

// round 16
// speedup vs baseline: 1.0954x; 1.0246x over previous
#include <cuda_runtime.h>
#include <math.h>

#define BATCH   1024
#define HALF    512
#define NT      10
#define PADDED  30
#define DEPTH   4
#define LAYERS  2
#define NHEADS  2
#define NCLS    10

typedef unsigned long long u64;

// g_mats layout (each matrix = 4 float2, row-major 2x2):
//   stem   : [0,120)    (t*4+l)*3+w
//   attn   : [120,600)  (((lay*2+h)*3+g)*4+l)*10+w
//   ffn    : [600,840)  ((lay*10+t)*4+l)*3+w
//   reduce : [840,960)  (t*4+l)*3+w
__device__ float2 g_mats[960 * 4];
__device__ float  g_H[BATCH * PADDED];
__device__ float  g_attn[BATCH * PADDED * NHEADS];

// ================= compile-time GF(2) mask tables =================
__host__ __device__ constexpr int parity(unsigned x) {
    int p = 0; while (x) { p ^= (int)(x & 1u); x >>= 1; } return p;
}

struct Masks {
    unsigned pm[DEPTH][NT];
    unsigned am[DEPTH][NT];
    unsigned zm[NT];
};

__host__ __device__ constexpr Masks make_masks() {
    Masks M{};
    for (int l = 0; l < DEPTH; l++) {
        unsigned R[NT]{}, Ri[NT]{};
        for (int u = 0; u < NT; u++) { R[u] = 1u << u; Ri[u] = 1u << u; }
        for (int ll = 0; ll < l; ll++) {
            int r = ll + 1;
            for (int i = 0; i < NT; i++) R[(i + r) % NT] ^= R[i];
        }
        for (int ll = l - 1; ll >= 0; ll--) {
            int r = ll + 1;
            for (int i = NT - 1; i >= 0; i--) Ri[(i + r) % NT] ^= Ri[i];
        }
        for (int w = 0; w < NT; w++) {
            unsigned m = 0;
            for (int u = 0; u < NT; u++) if ((Ri[u] >> w) & 1u) m |= 1u << u;
            M.pm[l][w] = m;
            M.am[l][w] = R[w];
        }
    }
    unsigned R[NT]{};
    for (int u = 0; u < NT; u++) R[u] = 1u << u;
    for (int ll = 0; ll < DEPTH; ll++) {
        int r = ll + 1;
        for (int i = 0; i < NT; i++) R[(i + r) % NT] ^= R[i];
    }
    for (int w = 0; w < NT; w++) M.zm[w] = R[w];
    return M;
}

struct Masks2 {
    unsigned pm[3][NT];
    unsigned am[3][NT];
    unsigned zm[NT];
    int posq[NT];
};

__host__ __device__ constexpr Masks2 make_masks2() {
    Masks M = make_masks();
    unsigned bestS = 0x1Fu; int bestScore = -1;
    for (unsigned S = 0; S < 1024u; S++) {
        int pc = 0;
        for (int q = 0; q < NT; q++) pc += (int)((S >> q) & 1u);
        if (pc != 5) continue;
        int score = 0;
        for (int l = 1; l < DEPTH; l++)
            for (int w = 0; w < NT; w++)
                if ((M.pm[l][w] & ~S & 0x3FFu) == 0u) score++;
        if (score > bestScore) { bestScore = score; bestS = S; }
    }
    int qpos[NT]{};
    Masks2 R{};
    {
        int lp = 0, hp = 5;
        for (int q = 0; q < NT; q++) {
            int p = ((bestS >> q) & 1u) ? lp++ : hp++;
            qpos[q] = p;
        }
        for (int q = 0; q < NT; q++) R.posq[qpos[q]] = q;
    }
    for (int l = 1; l < DEPTH; l++)
        for (int w = 0; w < NT; w++) {
            unsigned pm2 = 0, am2 = 0;
            for (int q = 0; q < NT; q++) {
                if ((M.pm[l][w] >> q) & 1u) pm2 |= 1u << qpos[q];
                if ((M.am[l][w] >> q) & 1u) am2 |= 1u << qpos[q];
            }
            R.pm[l - 1][w] = pm2;
            R.am[l - 1][w] = am2;
        }
    for (int w = 0; w < NT; w++) {
        unsigned z2 = 0;
        for (int q = 0; q < NT; q++) if ((M.zm[w] >> q) & 1u) z2 |= 1u << qpos[q];
        R.zm[w] = z2;
    }
    return R;
}
constexpr Masks2 MK2 = make_masks2();

// ================= packed f32x2 helpers =================
__device__ __forceinline__ u64 pack2(float lo, float hi) {
    u64 r; asm("mov.b64 %0, {%1,%2};" : "=l"(r) : "f"(lo), "f"(hi)); return r;
}
__device__ __forceinline__ float2 unpack2(u64 a) {
    float2 f; asm("mov.b64 {%0,%1}, %2;" : "=f"(f.x), "=f"(f.y) : "l"(a)); return f;
}
__device__ __forceinline__ u64 swap2(u64 a) {
    u64 r; asm("{ .reg .b32 lo, hi; mov.b64 {lo,hi}, %1; mov.b64 %0, {hi,lo}; }" : "=l"(r) : "l"(a)); return r;
}
__device__ __forceinline__ u64 f2fma(u64 a, u64 b, u64 c) {
    u64 r; asm("fma.rn.f32x2 %0, %1, %2, %3;" : "=l"(r) : "l"(a), "l"(b), "l"(c)); return r;
}
__device__ __forceinline__ u64 f2mul(u64 a, u64 b) {
    u64 r; asm("mul.rn.f32x2 %0, %1, %2;" : "=l"(r) : "l"(a), "l"(b)); return r;
}
__device__ __forceinline__ u64 shfl64_xor(u64 v, int m) {
    unsigned lo = (unsigned)v, hi = (unsigned)(v >> 32);
    lo = __shfl_xor_sync(0xffffffffu, lo, m);
    hi = __shfl_xor_sync(0xffffffffu, hi, m);
    return ((u64)hi << 32) | lo;
}

__device__ __forceinline__ float2 cmulf(float2 a, float2 b) {
    return make_float2(a.x * b.x - a.y * b.y, a.x * b.y + a.y * b.x);
}

// ================= SoA butterfly =================
__device__ __forceinline__ void soa_bfly(u64 xr, u64 xi, u64 yr, u64 yi,
                                         u64 CX, u64 cyp, u64 cyq, u64 dxp,
                                         u64 DYRE, u64 DYIM, u64& nr, u64& ni) {
    nr = f2fma(CX, xr, f2fma(cyp, xi, f2fma(dxp, yr, f2mul(DYRE, yi))));
    ni = f2fma(CX, xi, f2fma(cyq, xr, f2fma(dxp, yi, f2mul(DYIM, yr))));
}

// Case A: pure local, bit4 not in pair mask
template<unsigned MLO4, unsigned ALO4, int J>
__device__ __forceinline__ void loopA(u64* re, u64* im, u64 CX, u64 cy0, u64 cy1,
                                      u64 dx0, u64 dx1, u64 DYRE, u64 DYIM) {
    if constexpr (J < 16) {
        constexpr unsigned LOW = MLO4 & (0u - MLO4);
        if constexpr ((J & (int)LOW) == 0) {
            constexpr int J2 = J ^ (int)MLO4;
            constexpr int P  = parity(ALO4 & (unsigned)J);
            constexpr int P2 = parity(ALO4 & (unsigned)J2);
            u64 ar = re[J], ai = im[J], br = re[J2], bi = im[J2];
            u64 nr1, ni1, nr2, ni2;
            soa_bfly(ar, ai, br, bi, CX, P  ? cy1 : cy0, P  ? cy0 : cy1, P  ? dx1 : dx0, DYRE, DYIM, nr1, ni1);
            soa_bfly(br, bi, ar, ai, CX, P2 ? cy1 : cy0, P2 ? cy0 : cy1, P2 ? dx1 : dx0, DYRE, DYIM, nr2, ni2);
            re[J] = nr1; im[J] = ni1; re[J2] = nr2; im[J2] = ni2;
        }
        loopA<MLO4, ALO4, J + 1>(re, im, CX, cy0, cy1, dx0, dx1, DYRE, DYIM);
    }
}

// Case B: pair mask == bit4 only
template<unsigned ALO4, int J>
__device__ __forceinline__ void loopB(u64* re, u64* im, u64 CX, u64 cy0, u64 cy1,
                                      u64 dx0, u64 dx1, u64 DYRE, u64 DYIM) {
    if constexpr (J < 16) {
        constexpr int P = parity(ALO4 & (unsigned)J);
        u64 yr = swap2(re[J]), yi = swap2(im[J]);
        u64 nr, ni;
        soa_bfly(re[J], im[J], yr, yi, CX, P ? cy1 : cy0, P ? cy0 : cy1, P ? dx1 : dx0, DYRE, DYIM, nr, ni);
        re[J] = nr; im[J] = ni;
        loopB<ALO4, J + 1>(re, im, CX, cy0, cy1, dx0, dx1, DYRE, DYIM);
    }
}

// Case C: local with bit4 + low bits
template<unsigned MLO4, unsigned ALO4, int J>
__device__ __forceinline__ void loopC(u64* re, u64* im, u64 CX, u64 cy0, u64 cy1,
                                      u64 dx0, u64 dx1, u64 DYRE, u64 DYIM) {
    if constexpr (J < 16) {
        constexpr unsigned LOW = MLO4 & (0u - MLO4);
        if constexpr ((J & (int)LOW) == 0) {
            constexpr int J2 = J ^ (int)MLO4;
            constexpr int P  = parity(ALO4 & (unsigned)J);
            constexpr int P2 = parity(ALO4 & (unsigned)J2);
            u64 y1r = swap2(re[J2]), y1i = swap2(im[J2]);
            u64 y2r = swap2(re[J]),  y2i = swap2(im[J]);
            u64 nr1, ni1, nr2, ni2;
            soa_bfly(re[J],  im[J],  y1r, y1i, CX, P  ? cy1 : cy0, P  ? cy0 : cy1, P  ? dx1 : dx0, DYRE, DYIM, nr1, ni1);
            soa_bfly(re[J2], im[J2], y2r, y2i, CX, P2 ? cy1 : cy0, P2 ? cy0 : cy1, P2 ? dx1 : dx0, DYRE, DYIM, nr2, ni2);
            re[J] = nr1; im[J] = ni1; re[J2] = nr2; im[J2] = ni2;
        }
        loopC<MLO4, ALO4, J + 1>(re, im, CX, cy0, cy1, dx0, dx1, DYRE, DYIM);
    }
}

// Case D: lane bits only
template<unsigned MHI, unsigned MB4, unsigned ALO4, int J>
__device__ __forceinline__ void loopD(u64* re, u64* im, u64 CX, u64 cy0, u64 cy1,
                                      u64 dx0, u64 dx1, u64 DYRE, u64 DYIM) {
    if constexpr (J < 16) {
        constexpr int P = parity(ALO4 & (unsigned)J);
        u64 yr = shfl64_xor(re[J], (int)MHI);
        u64 yi = shfl64_xor(im[J], (int)MHI);
        if constexpr (MB4) { yr = swap2(yr); yi = swap2(yi); }
        u64 nr, ni;
        soa_bfly(re[J], im[J], yr, yi, CX, P ? cy1 : cy0, P ? cy0 : cy1, P ? dx1 : dx0, DYRE, DYIM, nr, ni);
        re[J] = nr; im[J] = ni;
        loopD<MHI, MB4, ALO4, J + 1>(re, im, CX, cy0, cy1, dx0, dx1, DYRE, DYIM);
    }
}

// Case F: lane + local bits
template<unsigned MLO4, unsigned MB4, unsigned MHI, unsigned ALO4, int J>
__device__ __forceinline__ void loopF(u64* re, u64* im, u64 CX, u64 cy0, u64 cy1,
                                      u64 dx0, u64 dx1, u64 DYRE, u64 DYIM) {
    if constexpr (J < 16) {
        constexpr unsigned LOW = MLO4 & (0u - MLO4);
        if constexpr ((J & (int)LOW) == 0) {
            constexpr int J2 = J ^ (int)MLO4;
            constexpr int P  = parity(ALO4 & (unsigned)J);
            constexpr int P2 = parity(ALO4 & (unsigned)J2);
            u64 y1r = shfl64_xor(re[J2], (int)MHI);
            u64 y1i = shfl64_xor(im[J2], (int)MHI);
            u64 y2r = shfl64_xor(re[J],  (int)MHI);
            u64 y2i = shfl64_xor(im[J],  (int)MHI);
            if constexpr (MB4) {
                y1r = swap2(y1r); y1i = swap2(y1i);
                y2r = swap2(y2r); y2i = swap2(y2i);
            }
            u64 nr1, ni1, nr2, ni2;
            soa_bfly(re[J],  im[J],  y1r, y1i, CX, P  ? cy1 : cy0, P  ? cy0 : cy1, P  ? dx1 : dx0, DYRE, DYIM, nr1, ni1);
            soa_bfly(re[J2], im[J2], y2r, y2i, CX, P2 ? cy1 : cy0, P2 ? cy0 : cy1, P2 ? dx1 : dx0, DYRE, DYIM, nr2, ni2);
            re[J] = nr1; im[J] = ni1; re[J2] = nr2; im[J2] = ni2;
        }
        loopF<MLO4, MB4, MHI, ALO4, J + 1>(re, im, CX, cy0, cy1, dx0, dx1, DYRE, DYIM);
    }
}

template<int L, int W>
__device__ __forceinline__ void apply_gate(u64* re, u64* im,
                                           const float2* __restrict__ gm, int lane) {
    constexpr unsigned m    = MK2.pm[L][W];
    constexpr unsigned a    = MK2.am[L][W];
    constexpr unsigned mlo4 = m & 15u;
    constexpr unsigned mb4  = (m >> 4) & 1u;
    constexpr unsigned mhi  = (m >> 5) & 31u;
    constexpr unsigned alo4 = a & 15u;
    constexpr unsigned ab4  = (a >> 4) & 1u;
    constexpr unsigned ahi  = (a >> 5) & 31u;
    float2 g00 = gm[((L + 1) * 10 + W) * 4 + 0];
    float2 g01 = gm[((L + 1) * 10 + W) * 4 + 1];
    float cx = g00.x, cy = g00.y, dx = g01.x, dy = g01.y;
    u64 CX   = pack2(cx, cx);
    u64 CY0  = pack2(-cy, ab4 ? cy : -cy);
    u64 DX0  = pack2(dx, ab4 ? -dx : dx);
    u64 DYRE = pack2(-dy, -dy);
    u64 DYIM = pack2(dy, dy);
    constexpr u64 SGN = 0x8000000080000000ull;
    u64 CY1 = CY0 ^ SGN;
    u64 DX1 = DX0 ^ SGN;
    int plane = (int)(__popc(ahi & (unsigned)lane) & 1);
    u64 cy0 = plane ? CY1 : CY0, cy1 = plane ? CY0 : CY1;
    u64 dx0 = plane ? DX1 : DX0, dx1 = plane ? DX0 : DX1;
    if constexpr (mhi == 0u && mb4 == 0u) {
        loopA<mlo4, alo4, 0>(re, im, CX, cy0, cy1, dx0, dx1, DYRE, DYIM);
    } else if constexpr (mhi == 0u && mlo4 == 0u) {
        loopB<alo4, 0>(re, im, CX, cy0, cy1, dx0, dx1, DYRE, DYIM);
    } else if constexpr (mhi == 0u) {
        loopC<mlo4, alo4, 0>(re, im, CX, cy0, cy1, dx0, dx1, DYRE, DYIM);
    } else if constexpr (mlo4 == 0u) {
        loopD<mhi, mb4, alo4, 0>(re, im, CX, cy0, cy1, dx0, dx1, DYRE, DYIM);
    } else {
        loopF<mlo4, mb4, mhi, alo4, 0>(re, im, CX, cy0, cy1, dx0, dx1, DYRE, DYIM);
    }
}

template<int G>
__device__ __forceinline__ void run_gates(u64* re, u64* im,
                                          const float2* __restrict__ gm, int lane) {
    if constexpr (G < 3 * NT) {
        apply_gate<G / NT, G % NT>(re, im, gm, lane);
        run_gates<G + 1>(re, im, gm, lane);
    }
}

// ================= measurement: packed |amp|^2 + packed FWHT =================
template<int K, int J>
__device__ __forceinline__ void fwht_stage_p(u64* pp, u64 ONE, u64 NEG) {
    if constexpr (J < 16) {
        if constexpr ((J & (1 << K)) == 0) {
            constexpr int J2 = J | (1 << K);
            u64 a = pp[J], b = pp[J2];
            pp[J]  = f2fma(ONE, b, a);
            pp[J2] = f2fma(NEG, b, a);
        }
        fwht_stage_p<K, J + 1>(pp, ONE, NEG);
    }
}
template<int K>
__device__ __forceinline__ void fwht_p(u64* pp, u64 ONE, u64 NEG) {
    if constexpr (K < 4) {
        fwht_stage_p<K, 0>(pp, ONE, NEG);
        fwht_p<K + 1>(pp, ONE, NEG);
    }
}
template<int W>
__device__ __forceinline__ void meas_from_p(const u64* pp, float* res, int lane) {
    if constexpr (W < NT) {
        constexpr unsigned z   = MK2.zm[W];
        constexpr unsigned idx = z & 15u;
        constexpr unsigned b4  = (z >> 4) & 1u;
        constexpr unsigned zhi = (z >> 5) & 31u;
        float2 v = unpack2(pp[idx]);
        float acc = b4 ? (v.x - v.y) : (v.x + v.y);
        if ((int)(__popc(zhi & (unsigned)lane) & 1)) acc = -acc;
        res[W] = acc;
        meas_from_p<W + 1>(pp, res, lane);
    }
}

// compile-time posq gather of embedding factors into position order
template<int P>
__device__ __forceinline__ void gather_factors(float2* fa, float2* fb, float2 va, float2 vb) {
    if constexpr (P < NT) {
        constexpr int q = MK2.posq[P];
        fa[P].x = __shfl_sync(0xffffffffu, va.x, q);
        fa[P].y = __shfl_sync(0xffffffffu, va.y, q);
        fb[P].x = __shfl_sync(0xffffffffu, vb.x, q);
        fb[P].y = __shfl_sync(0xffffffffu, vb.y, q);
        gather_factors<P + 1>(fa, fb, va, vb);
    }
}

// ================= 3-qubit register circuit (matrices from smem) =============
__device__ __forceinline__ float2 cadd3(float2 a, float2 b) {
    return make_float2(a.x + b.x, a.y + b.y);
}
__device__ __forceinline__ void run3(float x0, float x1, float x2,
                                     const float2* M, float E[3]) {
    float c[3], s[3];
    __sincosf(0.5f * x0, &s[0], &c[0]);
    __sincosf(0.5f * x1, &s[1], &c[1]);
    __sincosf(0.5f * x2, &s[2], &c[2]);
    float2 a[8];
#pragma unroll
    for (int i = 0; i < 8; i++) {
        float v = ((i >> 2) & 1 ? s[0] : c[0]) *
                  ((i >> 1) & 1 ? s[1] : c[1]) *
                  ((i      ) & 1 ? s[2] : c[2]);
        a[i] = make_float2(v, 0.f);
    }
#pragma unroll
    for (int l = 0; l < 4; l++) {
#pragma unroll
        for (int w = 0; w < 3; w++) {
            const float2* m = M + (l * 3 + w) * 4;
            const int p = 2 - w;
#pragma unroll
            for (int i0 = 0; i0 < 8; i0++) {
                if (i0 & (1 << p)) continue;
                int i1 = i0 | (1 << p);
                float2 A = a[i0], B = a[i1];
                a[i0] = cadd3(cmulf(m[0], A), cmulf(m[1], B));
                a[i1] = cadd3(cmulf(m[2], A), cmulf(m[3], B));
            }
        }
        const int r = (l & 1) + 1;
#pragma unroll
        for (int i = 0; i < 3; i++) {
            int pc = 2 - i;
            int pt = 2 - ((i + r) % 3);
#pragma unroll
            for (int idx = 0; idx < 8; idx++) {
                if (((idx >> pc) & 1) && !((idx >> pt) & 1)) {
                    int j = idx | (1 << pt);
                    float2 t = a[idx]; a[idx] = a[j]; a[j] = t;
                }
            }
        }
    }
    E[0] = E[1] = E[2] = 0.f;
#pragma unroll
    for (int i = 0; i < 8; i++) {
        float p = a[i].x * a[i].x + a[i].y * a[i].y;
        E[0] += (i & 4) ? -p : p;
        E[1] += (i & 2) ? -p : p;
        E[2] += (i & 1) ? -p : p;
    }
}

// ================= prep: Rot matrices =================
__global__ void prep_kernel(const float* __restrict__ t_stem,
                            const float* __restrict__ t_attn,
                            const float* __restrict__ t_ffn,
                            const float* __restrict__ t_red) {
    int i = blockIdx.x * blockDim.x + threadIdx.x;
    if (i < 960) {
        const float* a;
        if (i < 120)      a = t_stem + i * 3;
        else if (i < 600) a = t_attn + (i - 120) * 3;
        else if (i < 840) a = t_ffn  + (i - 600) * 3;
        else              a = t_red  + (i - 840) * 3;
        float phi = a[0], th = a[1], om = a[2];
        float c, s, cp, sp, cm, sm;
        sincosf(0.5f * th, &s, &c);
        sincosf(0.5f * (phi + om), &sp, &cp);
        sincosf(0.5f * (phi - om), &sm, &cm);
        float2* m = &g_mats[i * 4];
        m[0] = make_float2( cp * c, -sp * c);
        m[1] = make_float2(-cm * s, -sm * s);
        m[2] = make_float2( cm * s, -sm * s);
        m[3] = make_float2( cp * c,  sp * c);
    }
}

// ================= stem (half batch, offset boff, smem-staged mats) ==========
__global__ void stem_kernel(const float* __restrict__ x, int boff) {
    __shared__ float2 Ms[48];            // one token's 12 matrices
    int tid = threadIdx.x;
    int t = blockIdx.x >> 1;             // 2 blocks per token (256 thr = half of 512 b)
    if (tid < 48) Ms[tid] = g_mats[t * 48 + tid];
    __syncthreads();

    int i = blockIdx.x * blockDim.x + tid;   // [0, 5120)
    int b = boff + (i & 511);
    float E[3];
    run3(x[b * 30 + 3 * t], x[b * 30 + 3 * t + 1], x[b * 30 + 3 * t + 2], Ms, E);
#pragma unroll
    for (int k = 0; k < 3; k++) g_H[b * 30 + 3 * t + k] = E[k];
}

// ================= attention (half batch, occupancy-boosted) =================
__global__ void __launch_bounds__(128, 5) attn_kernel(int lay, int boff) {
    const int wid  = blockIdx.x * 4 + (threadIdx.x >> 5);   // [0, 3072)
    const int lane = threadIdx.x & 31;
    const int b  = boff + (wid & 511);
    const int hg = wid >> 9;                                 // [0, 6)
    const int h  = hg / 3, g = hg % 3;
    const float2* gm = g_mats + (120 + ((lay * 2 + h) * 3 + g) * 40) * 4;

    // ---- init: product state of V_q|0>, V_q = Rot(layer0,q) * RY(x_q) ----
    float2 va, vb;
    {
        int q = (lane < NT) ? lane : 0;
        float ang = (lane < NT) ? g_H[b * 30 + 3 * lane + g] : 0.f;
        float c, s;
        __sincosf(0.5f * ang, &s, &c);
        float2 g00 = gm[q * 4 + 0];
        float2 g01 = gm[q * 4 + 1];
        va = make_float2( g00.x * c + g01.x * s,  g00.y * c + g01.y * s);
        vb = make_float2(-g01.x * c + g00.x * s,  g01.y * c - g00.y * s);
    }
    float2 fa[NT], fb[NT];
    gather_factors<0>(fa, fb, va, vb);
    float2 lf = (lane & 1) ? fb[5] : fa[5];
#pragma unroll
    for (int p = 6; p < NT; p++)
        lf = cmulf(lf, ((lane >> (p - 5)) & 1) ? fb[p] : fa[p]);
    float2 T[16];
    T[0] = cmulf(lf, fa[0]);
    T[1] = cmulf(lf, fb[0]);
#pragma unroll
    for (int k = 1; k < 4; k++) {
#pragma unroll
        for (int j = 0; j < 8; j++) {
            if (j < (1 << k)) {
                T[j | (1 << k)] = cmulf(T[j], fb[k]);
                T[j]            = cmulf(T[j], fa[k]);
            }
        }
    }
    u64 re[16], im[16];
    {
        constexpr u64 SGN = 0x8000000080000000ull;
        u64 FRe  = pack2(fa[4].x, fb[4].x);
        u64 FIm  = pack2(fa[4].y, fb[4].y);
        u64 FImN = FIm ^ SGN;
#pragma unroll
        for (int j = 0; j < 16; j++) {
            u64 XX = pack2(T[j].x, T[j].x);
            u64 YY = pack2(T[j].y, T[j].y);
            re[j] = f2fma(XX, FRe, f2mul(YY, FImN));
            im[j] = f2fma(XX, FIm, f2mul(YY, FRe));
        }
    }

    run_gates<0>(re, im, gm, lane);

    u64 pp[16];
#pragma unroll
    for (int j = 0; j < 16; j++)
        pp[j] = f2fma(re[j], re[j], f2mul(im[j], im[j]));
    {
        u64 ONE = pack2(1.f, 1.f);
        u64 NEG = pack2(-1.f, -1.f);
        fwht_p<0>(pp, ONE, NEG);
    }
    float res[NT];
    meas_from_p<0>(pp, res, lane);
#pragma unroll
    for (int w = 0; w < NT; w++) {
#pragma unroll
        for (int off = 16; off; off >>= 1)
            res[w] += __shfl_xor_sync(0xffffffffu, res[w], off);
    }
    if (lane == 0) {
#pragma unroll
        for (int w = 0; w < NT; w++)
            g_attn[b * 60 + h * 30 + 3 * w + g] = res[w];
    }
}

// ====== fused W_O + residual + FFN (layer 0, half batch, smem-staged) ========
__global__ void wo_ffn_kernel(const float* __restrict__ W_O, int lay, int boff) {
    __shared__ float2 Ms[480];           // layer's 10 tokens x 12 matrices
    int tid = threadIdx.x;
    {
        const float4* src = (const float4*)(g_mats + (600 + lay * 120) * 4);
        float4* dst = (float4*)Ms;
        if (tid < 240) dst[tid] = src[tid];
    }
    __syncthreads();

    int gt = blockIdx.x * blockDim.x + tid;
    int b = boff + (gt >> 5), lane = gt & 31;

    float newH = 0.f;
    if (lane < 30) {
        const float4* wrow = (const float4*)(W_O + (lay * 30 + lane) * 60);
        const float4* arow = (const float4*)(g_attn + b * 60);
        float s0 = 0.f, s1 = 0.f, s2 = 0.f, s3 = 0.f;
#pragma unroll
        for (int k = 0; k < 15; k++) {
            float4 w4 = wrow[k];
            float4 a4 = arow[k];
            s0 = fmaf(a4.x, w4.x, s0);
            s1 = fmaf(a4.y, w4.y, s1);
            s2 = fmaf(a4.z, w4.z, s2);
            s3 = fmaf(a4.w, w4.w, s3);
        }
        newH = g_H[b * 30 + lane] + ((s0 + s1) + (s2 + s3));
    }
    __syncwarp();

    int f0 = 3 * lane, f1 = f0 + 1, f2 = f0 + 2;
    float in0 = __shfl_sync(0xffffffffu, newH, (3 * (f0 % 10) + f0 / 10) & 31);
    float in1 = __shfl_sync(0xffffffffu, newH, (3 * (f1 % 10) + f1 / 10) & 31);
    float in2 = __shfl_sync(0xffffffffu, newH, (3 * (f2 % 10) + f2 / 10) & 31);
    if (lane >= 10) { in0 = 0.f; in1 = 0.f; in2 = 0.f; }
    int t = (lane < 10) ? lane : 0;
    float E[3];
    run3(in0, in1, in2, Ms + t * 48, E);

    float h0 = __shfl_sync(0xffffffffu, newH, (3 * lane) & 31);
    float h1 = __shfl_sync(0xffffffffu, newH, (3 * lane + 1) & 31);
    float h2 = __shfl_sync(0xffffffffu, newH, (3 * lane + 2) & 31);
    if (lane < 10) {
        g_H[b * 30 + 3 * lane + 0] = h0 + E[0];
        g_H[b * 30 + 3 * lane + 1] = h1 + E[1];
        g_H[b * 30 + 3 * lane + 2] = h2 + E[2];
    }
}

// ===== layer-1 W_O + FFN + reduce + cls (half batch, smem-staged) ====
__global__ void wo_ffn_cls_kernel(const float* __restrict__ W_O,
                                  const float* __restrict__ Wc,
                                  const float* __restrict__ bc,
                                  float* __restrict__ out, int boff) {
    __shared__ float2 Mf[480];           // ffn layer-1 mats
    __shared__ float2 Mr[480];           // reduce mats
    int tid = threadIdx.x;
    {
        const float4* srcf = (const float4*)(g_mats + (600 + 120) * 4);
        const float4* srcr = (const float4*)(g_mats + 840 * 4);
        float4* dstf = (float4*)Mf;
        float4* dstr = (float4*)Mr;
        if (tid < 240) { dstf[tid] = srcf[tid]; dstr[tid] = srcr[tid]; }
    }
    __syncthreads();

    int gt = blockIdx.x * blockDim.x + tid;
    int b = boff + (gt >> 5), lane = gt & 31;
    const int lay = 1;

    float newH = 0.f;
    if (lane < 30) {
        const float4* wrow = (const float4*)(W_O + (lay * 30 + lane) * 60);
        const float4* arow = (const float4*)(g_attn + b * 60);
        float s0 = 0.f, s1 = 0.f, s2 = 0.f, s3 = 0.f;
#pragma unroll
        for (int k = 0; k < 15; k++) {
            float4 w4 = wrow[k];
            float4 a4 = arow[k];
            s0 = fmaf(a4.x, w4.x, s0);
            s1 = fmaf(a4.y, w4.y, s1);
            s2 = fmaf(a4.z, w4.z, s2);
            s3 = fmaf(a4.w, w4.w, s3);
        }
        newH = g_H[b * 30 + lane] + ((s0 + s1) + (s2 + s3));
    }
    __syncwarp();

    int f0 = 3 * lane, f1 = f0 + 1, f2 = f0 + 2;
    float in0 = __shfl_sync(0xffffffffu, newH, (3 * (f0 % 10) + f0 / 10) & 31);
    float in1 = __shfl_sync(0xffffffffu, newH, (3 * (f1 % 10) + f1 / 10) & 31);
    float in2 = __shfl_sync(0xffffffffu, newH, (3 * (f2 % 10) + f2 / 10) & 31);
    if (lane >= 10) { in0 = 0.f; in1 = 0.f; in2 = 0.f; }
    int t = (lane < 10) ? lane : 0;
    float E[3];
    run3(in0, in1, in2, Mf + t * 48, E);

    float h0 = __shfl_sync(0xffffffffu, newH, (3 * lane) & 31);
    float h1 = __shfl_sync(0xffffffffu, newH, (3 * lane + 1) & 31);
    float h2 = __shfl_sync(0xffffffffu, newH, (3 * lane + 2) & 31);

    float red = 0.f;
    {
        float hv0 = h0 + E[0], hv1 = h1 + E[1], hv2 = h2 + E[2];
        float R[3];
        run3(hv0, hv1, hv2, Mr + t * 48, R);
        if (lane < 10) red = R[0];
    }
    float rv[10];
#pragma unroll
    for (int tt = 0; tt < 10; tt++)
        rv[tt] = __shfl_sync(0xffffffffu, red, tt);
    if (lane < 10) {
        float s = bc[lane];
#pragma unroll
        for (int tt = 0; tt < 10; tt++) s = fmaf(rv[tt], Wc[lane * 10 + tt], s);
        out[b * 10 + lane] = s;
    }
}

// ================= launch: batch-split dual-stream pipeline =================
extern "C" void kernel_launch(void* const* d_in, const int* in_sizes, int n_in,
                              void* d_out, int out_size) {
    const float* x_      = (const float*)d_in[0];
    const float* t_stem  = (const float*)d_in[1];
    const float* t_attn  = (const float*)d_in[2];
    const float* W_O     = (const float*)d_in[3];
    const float* t_ffn   = (const float*)d_in[4];
    const float* t_red   = (const float*)d_in[5];
    const float* W_cls   = (const float*)d_in[6];
    const float* b_cls   = (const float*)d_in[7];
    float* out = (float*)d_out;

    static cudaStream_t s1 = nullptr;
    static cudaEvent_t  ef = nullptr, ej = nullptr;
    if (s1 == nullptr) {
        cudaStreamCreateWithFlags(&s1, cudaStreamNonBlocking);
        cudaEventCreateWithFlags(&ef, cudaEventDisableTiming);
        cudaEventCreateWithFlags(&ej, cudaEventDisableTiming);
    }

    prep_kernel<<<4, 256>>>(t_stem, t_attn, t_ffn, t_red);

    // fork: s1 waits for prep on the capture-origin (default) stream
    cudaEventRecord(ef, 0);
    cudaStreamWaitEvent(s1, ef, 0);

    // half A (b in [0,512)) on default stream
    stem_kernel<<<20, 256>>>(x_, 0);
    attn_kernel<<<768, 128>>>(0, 0);
    wo_ffn_kernel<<<64, 256>>>(W_O, 0, 0);
    attn_kernel<<<768, 128>>>(1, 0);
    wo_ffn_cls_kernel<<<64, 256>>>(W_O, W_cls, b_cls, out, 0);

    // half B (b in [512,1024)) on s1
    stem_kernel<<<20, 256, 0, s1>>>(x_, HALF);
    attn_kernel<<<768, 128, 0, s1>>>(0, HALF);
    wo_ffn_kernel<<<64, 256, 0, s1>>>(W_O, 0, HALF);
    attn_kernel<<<768, 128, 0, s1>>>(1, HALF);
    wo_ffn_cls_kernel<<<64, 256, 0, s1>>>(W_O, W_cls, b_cls, out, HALF);

    // join: default stream waits for s1
    cudaEventRecord(ej, s1);
    cudaStreamWaitEvent(0, ej, 0);
}